// round 1
// baseline (speedup 1.0000x reference)
#include <cuda_runtime.h>
#include <math.h>

// ---------------------------------------------------------------------------
// Problem constants
// ---------------------------------------------------------------------------
#define BATCH 4
#define FEAT_C 768          // 3 * 256 concatenated channels
#define FEAT_N 4096         // 64*64 spatial
#define EPS 1e-8f

// ---------------------------------------------------------------------------
// Device scratch (no allocations allowed)
// ---------------------------------------------------------------------------
__device__ float g_A[BATCH * 64 * 256 * 256];        // 64 MB ping
__device__ float g_B[BATCH * 64 * 256 * 256];        // 64 MB pong
__device__ float g_featraw[BATCH * FEAT_C * FEAT_N]; // [b][c][n]
__device__ float g_xn[BATCH * FEAT_N * FEAT_C];      // [b][n][c] normalized
__device__ float g_sn[BATCH * FEAT_N * FEAT_C];
__device__ float g_rnorm[BATCH * FEAT_N];            // 1/(||f||+eps)
__device__ float g_rowmax[BATCH * FEAT_N];

// ---------------------------------------------------------------------------
// Input normalization: (x - mean[c]) / std[c]
// ---------------------------------------------------------------------------
__global__ void normalize_input_kernel(const float* __restrict__ in, float* __restrict__ out) {
    const float mean[3] = {0.485f, 0.456f, 0.406f};
    const float stdv[3] = {0.229f, 0.224f, 0.225f};
    int total = BATCH * 3 * 256 * 256;
    for (int i = blockIdx.x * blockDim.x + threadIdx.x; i < total; i += gridDim.x * blockDim.x) {
        int c = (i >> 16) % 3;  // H*W = 65536
        out[i] = (in[i] - mean[c]) / stdv[c];
    }
}

// ---------------------------------------------------------------------------
// Direct 3x3 conv, pad 1, stride 1, + bias + ReLU
// Tile: 64 x-pixels x 16 y-rows x 8 output channels per block, 128 threads.
// Each thread: 8 consecutive x-pixels, 8 ocs -> 64 accumulators.
// ---------------------------------------------------------------------------
#define CV_BX 64
#define CV_BY 16
#define CV_TX 8
#define CV_PXT 8
#define CV_OCB 8
#define CV_ICS 4

__global__ __launch_bounds__(128)
void conv3x3_relu_kernel(const float* __restrict__ in, const float* __restrict__ wgt,
                         const float* __restrict__ bias, float* __restrict__ out,
                         int Cin, int Cout, int H, int W,
                         long in_bstride, long in_cstride,
                         long out_bstride, long out_cstride) {
    __shared__ float s_in[CV_ICS][CV_BY + 2][CV_BX + 2];
    __shared__ float s_w[CV_OCB][CV_ICS][9];

    int tid = threadIdx.x;
    int tx = tid % CV_TX;        // 0..7
    int ty = tid / CV_TX;        // 0..15
    int bx0 = blockIdx.x * CV_BX;
    int by0 = blockIdx.y * CV_BY;
    int ocg = Cout / CV_OCB;
    int b = blockIdx.z / ocg;
    int oc0 = (blockIdx.z % ocg) * CV_OCB;

    float acc[CV_OCB][CV_PXT];
#pragma unroll
    for (int o = 0; o < CV_OCB; o++)
#pragma unroll
        for (int p = 0; p < CV_PXT; p++) acc[o][p] = 0.f;

    const float* inb = in + (long)b * in_bstride;

    for (int ic0 = 0; ic0 < Cin; ic0 += CV_ICS) {
        int icn = Cin - ic0;
        if (icn > CV_ICS) icn = CV_ICS;

        // load input tile (with halo, zero padded)
        int tile = (CV_BY + 2) * (CV_BX + 2);
        int total = icn * tile;
        for (int i = tid; i < total; i += 128) {
            int ic = i / tile;
            int rem = i - ic * tile;
            int yy = rem / (CV_BX + 2);
            int xx = rem - yy * (CV_BX + 2);
            int gy = by0 + yy - 1;
            int gx = bx0 + xx - 1;
            float v = 0.f;
            if (gy >= 0 && gy < H && gx >= 0 && gx < W)
                v = inb[(long)(ic0 + ic) * in_cstride + (long)gy * W + gx];
            s_in[ic][yy][xx] = v;
        }
        // load weights [Cout][Cin][3][3]
        int wtotal = CV_OCB * icn * 9;
        for (int i = tid; i < wtotal; i += 128) {
            int oc = i / (icn * 9);
            int rem = i - oc * icn * 9;
            int ic = rem / 9;
            int k = rem - ic * 9;
            s_w[oc][ic][k] = wgt[((long)(oc0 + oc) * Cin + (ic0 + ic)) * 9 + k];
        }
        __syncthreads();

        for (int ic = 0; ic < icn; ic++) {
#pragma unroll
            for (int ky = 0; ky < 3; ky++) {
                float r[CV_PXT + 2];
#pragma unroll
                for (int j = 0; j < CV_PXT + 2; j++)
                    r[j] = s_in[ic][ty + ky][tx * CV_PXT + j];
#pragma unroll
                for (int kx = 0; kx < 3; kx++) {
                    float wv[CV_OCB];
#pragma unroll
                    for (int oc = 0; oc < CV_OCB; oc++) wv[oc] = s_w[oc][ic][ky * 3 + kx];
#pragma unroll
                    for (int oc = 0; oc < CV_OCB; oc++)
#pragma unroll
                        for (int p = 0; p < CV_PXT; p++)
                            acc[oc][p] = fmaf(wv[oc], r[p + kx], acc[oc][p]);
                }
            }
        }
        __syncthreads();
    }

    // bias + relu + store (2x float4 per oc)
    int gy = by0 + ty;
    int gx = bx0 + tx * CV_PXT;
#pragma unroll
    for (int oc = 0; oc < CV_OCB; oc++) {
        float bv = bias[oc0 + oc];
        float* op = out + (long)b * out_bstride + (long)(oc0 + oc) * out_cstride + (long)gy * W + gx;
#pragma unroll
        for (int p = 0; p < CV_PXT; p++) {
            float v = acc[oc][p] + bv;
            op[p] = v > 0.f ? v : 0.f;
        }
    }
}

// ---------------------------------------------------------------------------
// 2x2 max pool, stride 2
// ---------------------------------------------------------------------------
__global__ void maxpool2_kernel(const float* __restrict__ in, float* __restrict__ out,
                                int C, int H, int W) {
    int Ho = H >> 1, Wo = W >> 1;
    long total = (long)BATCH * C * Ho * Wo;
    for (long i = blockIdx.x * (long)blockDim.x + threadIdx.x; i < total;
         i += (long)gridDim.x * blockDim.x) {
        int x = (int)(i % Wo);
        long t = i / Wo;
        int y = (int)(t % Ho);
        long bc = t / Ho;
        const float* p = in + (bc * H + 2 * y) * (long)W + 2 * x;
        float m0 = fmaxf(p[0], p[1]);
        float m1 = fmaxf(p[W], p[W + 1]);
        out[i] = fmaxf(m0, m1);
    }
}

// ---------------------------------------------------------------------------
// Per-location channel norms of featraw [b][c][n] -> reciprocal denom
// ---------------------------------------------------------------------------
__global__ void norms_kernel(const float* __restrict__ raw, float* __restrict__ rnorm) {
    int i = blockIdx.x * blockDim.x + threadIdx.x;
    if (i >= BATCH * FEAT_N) return;
    int b = i >> 12;
    int n = i & (FEAT_N - 1);
    const float* p = raw + (long)b * FEAT_C * FEAT_N + n;
    float s = 0.f;
#pragma unroll 8
    for (int c = 0; c < FEAT_C; c++) {
        float v = p[(long)c * FEAT_N];
        s = fmaf(v, v, s);
    }
    rnorm[i] = 1.f / (sqrtf(s) + EPS);
}

// ---------------------------------------------------------------------------
// Transpose + scale: [b][c][n] -> [b][n][c] * rnorm[b][n]
// ---------------------------------------------------------------------------
__global__ void transpose_scale_kernel(const float* __restrict__ raw,
                                       const float* __restrict__ rnorm,
                                       float* __restrict__ outp) {
    __shared__ float t[32][33];
    int b = blockIdx.z;
    int c0 = blockIdx.x * 32;
    int n0 = blockIdx.y * 32;
    const float* rb = raw + (long)b * FEAT_C * FEAT_N;
#pragma unroll
    for (int j = 0; j < 32; j += 8)
        t[threadIdx.y + j][threadIdx.x] =
            rb[(long)(c0 + threadIdx.y + j) * FEAT_N + n0 + threadIdx.x];
    __syncthreads();
    float* ob = outp + (long)b * FEAT_N * FEAT_C;
#pragma unroll
    for (int j = 0; j < 32; j += 8) {
        int n = n0 + threadIdx.y + j;
        ob[(long)n * FEAT_C + c0 + threadIdx.x] =
            t[threadIdx.x][threadIdx.y + j] * rnorm[b * FEAT_N + n];
    }
}

// ---------------------------------------------------------------------------
// Row-max of xn @ sn^T  (per batch). Block: 32 n-rows, m in tiles of 128,
// c in chunks of 64, micro-tile 4n x 8m per thread (128 threads).
// ---------------------------------------------------------------------------
#define MD_CN 32
#define MD_MT 128
#define MD_CH 64

__global__ __launch_bounds__(128)
void maxdot_kernel(const float* __restrict__ xn, const float* __restrict__ sn,
                   float* __restrict__ rowmax) {
    __shared__ __align__(16) float sx[MD_CH][36];
    __shared__ __align__(16) float ss[MD_CH][132];
    __shared__ float spart[MD_CN][16];

    int tid = threadIdx.x;
    int tm = tid & 15;      // *8 m
    int tn = tid >> 4;      // *4 n
    int b = blockIdx.y;
    int n0 = blockIdx.x * MD_CN;
    const float* xb = xn + (long)b * FEAT_N * FEAT_C;
    const float* sb = sn + (long)b * FEAT_N * FEAT_C;

    float pmax[4] = {-1e30f, -1e30f, -1e30f, -1e30f};

    for (int m0 = 0; m0 < FEAT_N; m0 += MD_MT) {
        float acc[4][8];
#pragma unroll
        for (int i = 0; i < 4; i++)
#pragma unroll
            for (int j = 0; j < 8; j++) acc[i][j] = 0.f;

        for (int c0 = 0; c0 < FEAT_C; c0 += MD_CH) {
            // load x chunk [64c][32n] (transposed in smem)
            for (int s = tid; s < MD_CN * (MD_CH / 4); s += 128) {
                int nn = s >> 4;
                int c4 = (s & 15) * 4;
                float4 v = *(const float4*)(xb + (long)(n0 + nn) * FEAT_C + c0 + c4);
                sx[c4 + 0][nn] = v.x; sx[c4 + 1][nn] = v.y;
                sx[c4 + 2][nn] = v.z; sx[c4 + 3][nn] = v.w;
            }
            // load s chunk [64c][128m]
            for (int s = tid; s < MD_MT * (MD_CH / 4); s += 128) {
                int mm = s >> 4;
                int c4 = (s & 15) * 4;
                float4 v = *(const float4*)(sb + (long)(m0 + mm) * FEAT_C + c0 + c4);
                ss[c4 + 0][mm] = v.x; ss[c4 + 1][mm] = v.y;
                ss[c4 + 2][mm] = v.z; ss[c4 + 3][mm] = v.w;
            }
            __syncthreads();
#pragma unroll 4
            for (int cc = 0; cc < MD_CH; cc++) {
                float4 xv = *(const float4*)&sx[cc][tn * 4];
                float4 s0 = *(const float4*)&ss[cc][tm * 8];
                float4 s1 = *(const float4*)&ss[cc][tm * 8 + 4];
                float xa[4] = {xv.x, xv.y, xv.z, xv.w};
                float sv[8] = {s0.x, s0.y, s0.z, s0.w, s1.x, s1.y, s1.z, s1.w};
#pragma unroll
                for (int i = 0; i < 4; i++)
#pragma unroll
                    for (int j = 0; j < 8; j++)
                        acc[i][j] = fmaf(xa[i], sv[j], acc[i][j]);
            }
            __syncthreads();
        }
#pragma unroll
        for (int i = 0; i < 4; i++)
#pragma unroll
            for (int j = 0; j < 8; j++) pmax[i] = fmaxf(pmax[i], acc[i][j]);
    }

#pragma unroll
    for (int i = 0; i < 4; i++) spart[tn * 4 + i][tm] = pmax[i];
    __syncthreads();
    if (tid < MD_CN) {
        float m = spart[tid][0];
#pragma unroll
        for (int j = 1; j < 16; j++) m = fmaxf(m, spart[tid][j]);
        rowmax[b * FEAT_N + n0 + tid] = m;
    }
}

// ---------------------------------------------------------------------------
// Final reduction: mean(1 - rowmax)
// ---------------------------------------------------------------------------
__global__ void loss_kernel(const float* __restrict__ rowmax, float* __restrict__ out) {
    __shared__ float sred[256];
    float s = 0.f;
    for (int i = threadIdx.x; i < BATCH * FEAT_N; i += 256)
        s += 1.0f - rowmax[i];
    sred[threadIdx.x] = s;
    __syncthreads();
    for (int k = 128; k > 0; k >>= 1) {
        if (threadIdx.x < k) sred[threadIdx.x] += sred[threadIdx.x + k];
        __syncthreads();
    }
    if (threadIdx.x == 0) out[0] = sred[0] / (float)(BATCH * FEAT_N);
}

// ---------------------------------------------------------------------------
// Host orchestration
// ---------------------------------------------------------------------------
static void launch_conv(const float* in, const float* w, const float* b, float* out,
                        int Cin, int Cout, int H, int W,
                        long in_bs, long in_cs, long out_bs, long out_cs) {
    dim3 grid(W / CV_BX, H / CV_BY, BATCH * (Cout / CV_OCB));
    conv3x3_relu_kernel<<<grid, 128>>>(in, w, b, out, Cin, Cout, H, W,
                                       in_bs, in_cs, out_bs, out_cs);
}

static void run_features(const float* img,
                         const float* const* w, const float* const* bi,
                         float* A, float* B, float* featraw, float* rnorm,
                         float* featnorm) {
    // normalize input -> A [4,3,256,256]
    normalize_input_kernel<<<512, 256>>>(img, A);
    long HW256 = 256L * 256, HW128 = 128L * 128, HW64 = 64L * 64;

    launch_conv(A, w[0], bi[0], B, 3, 64, 256, 256, 3 * HW256, HW256, 64 * HW256, HW256);
    launch_conv(B, w[1], bi[1], A, 64, 64, 256, 256, 64 * HW256, HW256, 64 * HW256, HW256);
    maxpool2_kernel<<<2048, 256>>>(A, B, 64, 256, 256);               // -> [4,64,128,128]
    launch_conv(B, w[2], bi[2], A, 64, 128, 128, 128, 64 * HW128, HW128, 128 * HW128, HW128);
    launch_conv(A, w[3], bi[3], B, 128, 128, 128, 128, 128 * HW128, HW128, 128 * HW128, HW128);
    maxpool2_kernel<<<1024, 256>>>(B, A, 128, 128, 128);              // -> [4,128,64,64]

    long fb = (long)FEAT_C * FEAT_N;  // featraw batch stride
    launch_conv(A, w[4], bi[4], featraw, 128, 256, 64, 64,
                128 * HW64, HW64, fb, HW64);                          // f1 -> ch 0..255
    launch_conv(featraw, w[5], bi[5], featraw + 256L * FEAT_N, 256, 256, 64, 64,
                fb, HW64, fb, HW64);                                  // f2 -> ch 256..511
    launch_conv(featraw + 256L * FEAT_N, w[6], bi[6], featraw + 512L * FEAT_N,
                256, 256, 64, 64, fb, HW64, fb, HW64);                // f3 -> ch 512..767

    norms_kernel<<<(BATCH * FEAT_N + 255) / 256, 256>>>(featraw, rnorm);
    dim3 tg(FEAT_C / 32, FEAT_N / 32, BATCH);
    transpose_scale_kernel<<<tg, dim3(32, 8)>>>(featraw, rnorm, featnorm);
}

extern "C" void kernel_launch(void* const* d_in, const int* in_sizes, int n_in,
                              void* d_out, int out_size) {
    const float* outputs = (const float*)d_in[0];
    const float* styles  = (const float*)d_in[1];
    const float* w[7];
    const float* bi[7];
    for (int i = 0; i < 7; i++) {
        w[i]  = (const float*)d_in[2 + 2 * i];
        bi[i] = (const float*)d_in[3 + 2 * i];
    }

    float *A, *B, *featraw, *xn, *sn, *rnorm, *rowmax;
    cudaGetSymbolAddress((void**)&A, g_A);
    cudaGetSymbolAddress((void**)&B, g_B);
    cudaGetSymbolAddress((void**)&featraw, g_featraw);
    cudaGetSymbolAddress((void**)&xn, g_xn);
    cudaGetSymbolAddress((void**)&sn, g_sn);
    cudaGetSymbolAddress((void**)&rnorm, g_rnorm);
    cudaGetSymbolAddress((void**)&rowmax, g_rowmax);

    run_features(outputs, w, bi, A, B, featraw, rnorm, xn);
    run_features(styles,  w, bi, A, B, featraw, rnorm, sn);

    dim3 mg(FEAT_N / MD_CN, BATCH);
    maxdot_kernel<<<mg, 128>>>(xn, sn, rowmax);
    loss_kernel<<<1, 256>>>(rowmax, (float*)d_out);
}

// round 6
// speedup vs baseline: 1.4312x; 1.4312x over previous
#include <cuda_runtime.h>
#include <cuda_fp16.h>
#include <math.h>
#include <stdint.h>

// ---------------------------------------------------------------------------
// Problem constants
// ---------------------------------------------------------------------------
#define BATCH 4
#define FEAT_C 768          // 3 * 256 concatenated channels
#define FEAT_N 4096         // 64*64 spatial
#define EPS 1e-8f

// ---------------------------------------------------------------------------
// Device scratch (no allocations allowed)
// ---------------------------------------------------------------------------
__device__ float g_A[BATCH * 64 * 256 * 256];        // 64 MB ping
__device__ float g_B[BATCH * 64 * 256 * 256];        // 64 MB pong
__device__ float g_featraw[BATCH * FEAT_C * FEAT_N]; // [b][c][n]
__device__ float g_xn[BATCH * FEAT_N * FEAT_C];      // [b][n][c] normalized fp32
__device__ float g_sn[BATCH * FEAT_N * FEAT_C];
__device__ __half g_xh[BATCH * FEAT_N * FEAT_C];     // fp16 copies for tensor cores
__device__ __half g_sh[BATCH * FEAT_N * FEAT_C];
__device__ float g_rnorm[BATCH * FEAT_N];            // 1/(||f||+eps)
__device__ float g_rowmax[BATCH * FEAT_N];
__device__ int2  g_cand[BATCH * FEAT_N];             // top-2 candidate indices

// ---------------------------------------------------------------------------
// Input normalization: (x - mean[c]) / std[c]
// ---------------------------------------------------------------------------
__global__ void normalize_input_kernel(const float* __restrict__ in, float* __restrict__ out) {
    const float mean[3] = {0.485f, 0.456f, 0.406f};
    const float stdv[3] = {0.229f, 0.224f, 0.225f};
    int total = BATCH * 3 * 256 * 256;
    for (int i = blockIdx.x * blockDim.x + threadIdx.x; i < total; i += gridDim.x * blockDim.x) {
        int c = (i >> 16) % 3;
        out[i] = (in[i] - mean[c]) / stdv[c];
    }
}

// ---------------------------------------------------------------------------
// Direct 3x3 conv, pad 1, stride 1, + bias + ReLU (unchanged from R1)
// ---------------------------------------------------------------------------
#define CV_BX 64
#define CV_BY 16
#define CV_TX 8
#define CV_PXT 8
#define CV_OCB 8
#define CV_ICS 4

__global__ __launch_bounds__(128)
void conv3x3_relu_kernel(const float* __restrict__ in, const float* __restrict__ wgt,
                         const float* __restrict__ bias, float* __restrict__ out,
                         int Cin, int Cout, int H, int W,
                         long in_bstride, long in_cstride,
                         long out_bstride, long out_cstride) {
    __shared__ float s_in[CV_ICS][CV_BY + 2][CV_BX + 2];
    __shared__ float s_w[CV_OCB][CV_ICS][9];

    int tid = threadIdx.x;
    int tx = tid % CV_TX;
    int ty = tid / CV_TX;
    int bx0 = blockIdx.x * CV_BX;
    int by0 = blockIdx.y * CV_BY;
    int ocg = Cout / CV_OCB;
    int b = blockIdx.z / ocg;
    int oc0 = (blockIdx.z % ocg) * CV_OCB;

    float acc[CV_OCB][CV_PXT];
#pragma unroll
    for (int o = 0; o < CV_OCB; o++)
#pragma unroll
        for (int p = 0; p < CV_PXT; p++) acc[o][p] = 0.f;

    const float* inb = in + (long)b * in_bstride;

    for (int ic0 = 0; ic0 < Cin; ic0 += CV_ICS) {
        int icn = Cin - ic0;
        if (icn > CV_ICS) icn = CV_ICS;

        int tile = (CV_BY + 2) * (CV_BX + 2);
        int total = icn * tile;
        for (int i = tid; i < total; i += 128) {
            int ic = i / tile;
            int rem = i - ic * tile;
            int yy = rem / (CV_BX + 2);
            int xx = rem - yy * (CV_BX + 2);
            int gy = by0 + yy - 1;
            int gx = bx0 + xx - 1;
            float v = 0.f;
            if (gy >= 0 && gy < H && gx >= 0 && gx < W)
                v = inb[(long)(ic0 + ic) * in_cstride + (long)gy * W + gx];
            s_in[ic][yy][xx] = v;
        }
        int wtotal = CV_OCB * icn * 9;
        for (int i = tid; i < wtotal; i += 128) {
            int oc = i / (icn * 9);
            int rem = i - oc * icn * 9;
            int ic = rem / 9;
            int k = rem - ic * 9;
            s_w[oc][ic][k] = wgt[((long)(oc0 + oc) * Cin + (ic0 + ic)) * 9 + k];
        }
        __syncthreads();

        for (int ic = 0; ic < icn; ic++) {
#pragma unroll
            for (int ky = 0; ky < 3; ky++) {
                float r[CV_PXT + 2];
#pragma unroll
                for (int j = 0; j < CV_PXT + 2; j++)
                    r[j] = s_in[ic][ty + ky][tx * CV_PXT + j];
#pragma unroll
                for (int kx = 0; kx < 3; kx++) {
                    float wv[CV_OCB];
#pragma unroll
                    for (int oc = 0; oc < CV_OCB; oc++) wv[oc] = s_w[oc][ic][ky * 3 + kx];
#pragma unroll
                    for (int oc = 0; oc < CV_OCB; oc++)
#pragma unroll
                        for (int p = 0; p < CV_PXT; p++)
                            acc[oc][p] = fmaf(wv[oc], r[p + kx], acc[oc][p]);
                }
            }
        }
        __syncthreads();
    }

    int gy = by0 + ty;
    int gx = bx0 + tx * CV_PXT;
#pragma unroll
    for (int oc = 0; oc < CV_OCB; oc++) {
        float bv = bias[oc0 + oc];
        float* op = out + (long)b * out_bstride + (long)(oc0 + oc) * out_cstride + (long)gy * W + gx;
#pragma unroll
        for (int p = 0; p < CV_PXT; p++) {
            float v = acc[oc][p] + bv;
            op[p] = v > 0.f ? v : 0.f;
        }
    }
}

// ---------------------------------------------------------------------------
// 2x2 max pool, stride 2
// ---------------------------------------------------------------------------
__global__ void maxpool2_kernel(const float* __restrict__ in, float* __restrict__ out,
                                int C, int H, int W) {
    int Ho = H >> 1, Wo = W >> 1;
    long total = (long)BATCH * C * Ho * Wo;
    for (long i = blockIdx.x * (long)blockDim.x + threadIdx.x; i < total;
         i += (long)gridDim.x * blockDim.x) {
        int x = (int)(i % Wo);
        long t = i / Wo;
        int y = (int)(t % Ho);
        long bc = t / Ho;
        const float* p = in + (bc * H + 2 * y) * (long)W + 2 * x;
        float m0 = fmaxf(p[0], p[1]);
        float m1 = fmaxf(p[W], p[W + 1]);
        out[i] = fmaxf(m0, m1);
    }
}

// ---------------------------------------------------------------------------
// Per-location channel norms of featraw [b][c][n] -> reciprocal denom
// ---------------------------------------------------------------------------
__global__ void norms_kernel(const float* __restrict__ raw, float* __restrict__ rnorm) {
    int i = blockIdx.x * blockDim.x + threadIdx.x;
    if (i >= BATCH * FEAT_N) return;
    int b = i >> 12;
    int n = i & (FEAT_N - 1);
    const float* p = raw + (long)b * FEAT_C * FEAT_N + n;
    float s = 0.f;
#pragma unroll 8
    for (int c = 0; c < FEAT_C; c++) {
        float v = p[(long)c * FEAT_N];
        s = fmaf(v, v, s);
    }
    rnorm[i] = 1.f / (sqrtf(s) + EPS);
}

// ---------------------------------------------------------------------------
// Transpose + scale: [b][c][n] -> [b][n][c] * rnorm[b][n]; fp32 + fp16 outputs
// ---------------------------------------------------------------------------
__global__ void transpose_scale_kernel(const float* __restrict__ raw,
                                       const float* __restrict__ rnorm,
                                       float* __restrict__ outp,
                                       __half* __restrict__ outh) {
    __shared__ float t[32][33];
    int b = blockIdx.z;
    int c0 = blockIdx.x * 32;
    int n0 = blockIdx.y * 32;
    const float* rb = raw + (long)b * FEAT_C * FEAT_N;
#pragma unroll
    for (int j = 0; j < 32; j += 8)
        t[threadIdx.y + j][threadIdx.x] =
            rb[(long)(c0 + threadIdx.y + j) * FEAT_N + n0 + threadIdx.x];
    __syncthreads();
    float* ob = outp + (long)b * FEAT_N * FEAT_C;
    __half* hb = outh + (long)b * FEAT_N * FEAT_C;
#pragma unroll
    for (int j = 0; j < 32; j += 8) {
        int n = n0 + threadIdx.y + j;
        float v = t[threadIdx.x][threadIdx.y + j] * rnorm[b * FEAT_N + n];
        ob[(long)n * FEAT_C + c0 + threadIdx.x] = v;
        hb[(long)n * FEAT_C + c0 + threadIdx.x] = __float2half(v);
    }
}

// ---------------------------------------------------------------------------
// HMMA candidate search via mma.sync (portable, no tcgen05).
// Block: 256 thr (8 warps). Tile 128n x 128m, warp tile 32n x 64m, K chunk 32.
// B fragment: sB is [n][k] row-major (k contiguous) -> NON-trans ldmatrix gives
// lane l -> (n = l/4, k = 2*(l%4)+{0,1}), exactly the mma.row.col B layout.
// Tracks per-row top-2 (value, index); exact fp32 rescore afterwards.
// ---------------------------------------------------------------------------
__device__ __forceinline__ uint32_t smem_addr32(const void* p) {
    return (uint32_t)__cvta_generic_to_shared(p);
}

__device__ __forceinline__ void ldm_x4(uint32_t addr, uint32_t r[4]) {
    asm volatile("ldmatrix.sync.aligned.m8n8.x4.shared.b16 {%0,%1,%2,%3}, [%4];"
                 : "=r"(r[0]), "=r"(r[1]), "=r"(r[2]), "=r"(r[3]) : "r"(addr));
}
__device__ __forceinline__ void mma16816(float d[4], const uint32_t a[4],
                                         uint32_t b0, uint32_t b1) {
    asm volatile(
        "mma.sync.aligned.m16n8k16.row.col.f32.f16.f16.f32 "
        "{%0,%1,%2,%3}, {%4,%5,%6,%7}, {%8,%9}, {%0,%1,%2,%3};"
        : "+f"(d[0]), "+f"(d[1]), "+f"(d[2]), "+f"(d[3])
        : "r"(a[0]), "r"(a[1]), "r"(a[2]), "r"(a[3]), "r"(b0), "r"(b1));
}

// merge top2 (a) <- union(a, b)
__device__ __forceinline__ void merge_top2(float& a1, int& ai1, float& a2, int& ai2,
                                           float b1, int bi1, float b2, int bi2) {
    if (b1 > a1) {
        float tv = a1; int ti = ai1;
        a1 = b1; ai1 = bi1;
        b1 = tv; bi1 = ti;
        if (b2 > a2) { a2 = b2; ai2 = bi2; }
    }
    if (b1 > a2) { a2 = b1; ai2 = bi1; }
}

#define MM_PAD 40   // halves per smem row (32 data + 8 pad)

__global__ __launch_bounds__(256)
void maxdot_mma_kernel(const __half* __restrict__ xh, const __half* __restrict__ sh,
                       int2* __restrict__ cand) {
    __shared__ __half sA[128][MM_PAD];
    __shared__ __half sB[128][MM_PAD];
    __shared__ float sVal[128][4];
    __shared__ int   sIdx[128][4];

    int tid = threadIdx.x;
    int lane = tid & 31;
    int wid = tid >> 5;
    int wn = wid & 3;      // warp n-tile (32 rows)
    int wm = wid >> 2;     // warp m-tile (64 cols)
    int b = blockIdx.y;
    int n0 = blockIdx.x * 128;

    // persistent per-thread top2 for 4 row-slots
    float t1[4], t2[4];
    int i1[4], i2[4];
#pragma unroll
    for (int s = 0; s < 4; s++) { t1[s] = -1e30f; t2[s] = -1e30f; i1[s] = 0; i2[s] = 0; }

    int ldrow = tid >> 1;
    int ldseg = tid & 1;
    const __half* xrow = xh + ((long)(b * FEAT_N + n0 + ldrow)) * FEAT_C + ldseg * 16;

    // ldmatrix lane->address maps (A fragment and B fragment, both non-trans)
    int a_row = (lane & 15);
    int a_col8 = (lane >> 4) * 8;
    int b_row = (lane & 7) + ((lane >> 4) * 8);   // n within 16-row group
    int b_col8 = ((lane >> 3) & 1) * 8;           // k 8-segment

    for (int mt = 0; mt < 32; mt++) {
        float d[2][8][4];
#pragma unroll
        for (int mf = 0; mf < 2; mf++)
#pragma unroll
            for (int nf = 0; nf < 8; nf++)
#pragma unroll
                for (int e = 0; e < 4; e++) d[mf][nf][e] = 0.f;

        const __half* srow = sh + ((long)(b * FEAT_N + mt * 128 + ldrow)) * FEAT_C + ldseg * 16;

        for (int kc = 0; kc < 24; kc++) {
            // load A and B 128x32 chunks
            const uint4* xp = (const uint4*)(xrow + kc * 32);
            const uint4* spp = (const uint4*)(srow + kc * 32);
            uint4 va0 = xp[0], va1 = xp[1];
            uint4 vb0 = spp[0], vb1 = spp[1];
            *(uint4*)&sA[ldrow][ldseg * 16] = va0;
            *(uint4*)&sA[ldrow][ldseg * 16 + 8] = va1;
            *(uint4*)&sB[ldrow][ldseg * 16] = vb0;
            *(uint4*)&sB[ldrow][ldseg * 16 + 8] = vb1;
            __syncthreads();

#pragma unroll
            for (int ks = 0; ks < 2; ks++) {
                uint32_t bf[4][4];
#pragma unroll
                for (int p = 0; p < 4; p++) {
                    uint32_t ad = smem_addr32(&sB[wm * 64 + p * 16 + b_row][ks * 16 + b_col8]);
                    ldm_x4(ad, bf[p]);   // non-trans: B fragment from [n][k] smem
                }
#pragma unroll
                for (int mf = 0; mf < 2; mf++) {
                    uint32_t af[4];
                    uint32_t ad = smem_addr32(&sA[wn * 32 + mf * 16 + a_row][ks * 16 + a_col8]);
                    ldm_x4(ad, af);
#pragma unroll
                    for (int p = 0; p < 4; p++) {
                        mma16816(d[mf][2 * p],     af, bf[p][0], bf[p][1]);
                        mma16816(d[mf][2 * p + 1], af, bf[p][2], bf[p][3]);
                    }
                }
            }
            __syncthreads();
        }

        // fold this m-tile's sims into persistent top2
#pragma unroll
        for (int mf = 0; mf < 2; mf++)
#pragma unroll
            for (int nf = 0; nf < 8; nf++) {
                int colb = mt * 128 + wm * 64 + nf * 8 + (lane & 3) * 2;
#pragma unroll
                for (int e = 0; e < 4; e++) {
                    int s = mf * 2 + (e >> 1);
                    float v = d[mf][nf][e];
                    int m = colb + (e & 1);
                    if (v > t1[s]) { t2[s] = t1[s]; i2[s] = i1[s]; t1[s] = v; i1[s] = m; }
                    else if (v > t2[s]) { t2[s] = v; i2[s] = m; }
                }
            }
    }

    // quad butterfly merge (lanes differing in low 2 bits share the same rows)
#pragma unroll
    for (int off = 1; off <= 2; off <<= 1) {
#pragma unroll
        for (int s = 0; s < 4; s++) {
            float o1 = __shfl_xor_sync(0xFFFFFFFF, t1[s], off);
            float o2 = __shfl_xor_sync(0xFFFFFFFF, t2[s], off);
            int oi1 = __shfl_xor_sync(0xFFFFFFFF, i1[s], off);
            int oi2 = __shfl_xor_sync(0xFFFFFFFF, i2[s], off);
            merge_top2(t1[s], i1[s], t2[s], i2[s], o1, oi1, o2, oi2);
        }
    }

    if ((lane & 3) == 0) {
#pragma unroll
        for (int s = 0; s < 4; s++) {
            int mf = s >> 1;
            int hi = s & 1;
            int row = wn * 32 + mf * 16 + (lane >> 2) + hi * 8;
            sVal[row][wm * 2 + 0] = t1[s];
            sVal[row][wm * 2 + 1] = t2[s];
            sIdx[row][wm * 2 + 0] = i1[s];
            sIdx[row][wm * 2 + 1] = i2[s];
        }
    }
    __syncthreads();

    if (tid < 128) {
        float a1 = sVal[tid][0], a2 = sVal[tid][1];
        int ai1 = sIdx[tid][0], ai2 = sIdx[tid][1];
        merge_top2(a1, ai1, a2, ai2, sVal[tid][2], sIdx[tid][2], sVal[tid][3], sIdx[tid][3]);
        cand[b * FEAT_N + n0 + tid] = make_int2(ai1, ai2);
    }
}

// ---------------------------------------------------------------------------
// Exact fp32 rescore of top-2 candidates -> rowmax
// ---------------------------------------------------------------------------
__global__ void rescore_kernel(const float* __restrict__ xn, const float* __restrict__ sn,
                               const int2* __restrict__ cand, float* __restrict__ rowmax) {
    int gwarp = (blockIdx.x * blockDim.x + threadIdx.x) >> 5;
    int lane = threadIdx.x & 31;
    if (gwarp >= BATCH * FEAT_N) return;
    int b = gwarp >> 12;
    int2 c = cand[gwarp];
    const float4* xr = (const float4*)(xn + (long)gwarp * FEAT_C);
    const float4* s1 = (const float4*)(sn + ((long)(b << 12) + c.x) * FEAT_C);
    const float4* s2 = (const float4*)(sn + ((long)(b << 12) + c.y) * FEAT_C);
    float d1 = 0.f, d2 = 0.f;
#pragma unroll
    for (int i = 0; i < 6; i++) {
        int k = i * 32 + lane;
        float4 xv = xr[k], a = s1[k], bb = s2[k];
        d1 += xv.x * a.x + xv.y * a.y + xv.z * a.z + xv.w * a.w;
        d2 += xv.x * bb.x + xv.y * bb.y + xv.z * bb.z + xv.w * bb.w;
    }
#pragma unroll
    for (int off = 16; off > 0; off >>= 1) {
        d1 += __shfl_xor_sync(0xFFFFFFFF, d1, off);
        d2 += __shfl_xor_sync(0xFFFFFFFF, d2, off);
    }
    if (lane == 0) rowmax[gwarp] = fmaxf(d1, d2);
}

// ---------------------------------------------------------------------------
// Final reduction: mean(1 - rowmax)
// ---------------------------------------------------------------------------
__global__ void loss_kernel(const float* __restrict__ rowmax, float* __restrict__ out) {
    __shared__ float sred[256];
    float s = 0.f;
    for (int i = threadIdx.x; i < BATCH * FEAT_N; i += 256)
        s += 1.0f - rowmax[i];
    sred[threadIdx.x] = s;
    __syncthreads();
    for (int k = 128; k > 0; k >>= 1) {
        if (threadIdx.x < k) sred[threadIdx.x] += sred[threadIdx.x + k];
        __syncthreads();
    }
    if (threadIdx.x == 0) out[0] = sred[0] / (float)(BATCH * FEAT_N);
}

// ---------------------------------------------------------------------------
// Host orchestration
// ---------------------------------------------------------------------------
static void launch_conv(const float* in, const float* w, const float* b, float* out,
                        int Cin, int Cout, int H, int W,
                        long in_bs, long in_cs, long out_bs, long out_cs) {
    dim3 grid(W / CV_BX, H / CV_BY, BATCH * (Cout / CV_OCB));
    conv3x3_relu_kernel<<<grid, 128>>>(in, w, b, out, Cin, Cout, H, W,
                                       in_bs, in_cs, out_bs, out_cs);
}

static void run_features(const float* img,
                         const float* const* w, const float* const* bi,
                         float* A, float* B, float* featraw, float* rnorm,
                         float* featnorm, __half* feathalf) {
    normalize_input_kernel<<<512, 256>>>(img, A);
    long HW256 = 256L * 256, HW128 = 128L * 128, HW64 = 64L * 64;

    launch_conv(A, w[0], bi[0], B, 3, 64, 256, 256, 3 * HW256, HW256, 64 * HW256, HW256);
    launch_conv(B, w[1], bi[1], A, 64, 64, 256, 256, 64 * HW256, HW256, 64 * HW256, HW256);
    maxpool2_kernel<<<2048, 256>>>(A, B, 64, 256, 256);
    launch_conv(B, w[2], bi[2], A, 64, 128, 128, 128, 64 * HW128, HW128, 128 * HW128, HW128);
    launch_conv(A, w[3], bi[3], B, 128, 128, 128, 128, 128 * HW128, HW128, 128 * HW128, HW128);
    maxpool2_kernel<<<1024, 256>>>(B, A, 128, 128, 128);

    long fb = (long)FEAT_C * FEAT_N;
    launch_conv(A, w[4], bi[4], featraw, 128, 256, 64, 64,
                128 * HW64, HW64, fb, HW64);
    launch_conv(featraw, w[5], bi[5], featraw + 256L * FEAT_N, 256, 256, 64, 64,
                fb, HW64, fb, HW64);
    launch_conv(featraw + 256L * FEAT_N, w[6], bi[6], featraw + 512L * FEAT_N,
                256, 256, 64, 64, fb, HW64, fb, HW64);

    norms_kernel<<<(BATCH * FEAT_N + 255) / 256, 256>>>(featraw, rnorm);
    dim3 tg(FEAT_C / 32, FEAT_N / 32, BATCH);
    transpose_scale_kernel<<<tg, dim3(32, 8)>>>(featraw, rnorm, featnorm, feathalf);
}

extern "C" void kernel_launch(void* const* d_in, const int* in_sizes, int n_in,
                              void* d_out, int out_size) {
    const float* outputs = (const float*)d_in[0];
    const float* styles  = (const float*)d_in[1];
    const float* w[7];
    const float* bi[7];
    for (int i = 0; i < 7; i++) {
        w[i]  = (const float*)d_in[2 + 2 * i];
        bi[i] = (const float*)d_in[3 + 2 * i];
    }

    float *A, *B, *featraw, *xn, *sn, *rnorm, *rowmax;
    __half *xhh, *shh;
    int2* cand;
    cudaGetSymbolAddress((void**)&A, g_A);
    cudaGetSymbolAddress((void**)&B, g_B);
    cudaGetSymbolAddress((void**)&featraw, g_featraw);
    cudaGetSymbolAddress((void**)&xn, g_xn);
    cudaGetSymbolAddress((void**)&sn, g_sn);
    cudaGetSymbolAddress((void**)&xhh, g_xh);
    cudaGetSymbolAddress((void**)&shh, g_sh);
    cudaGetSymbolAddress((void**)&rnorm, g_rnorm);
    cudaGetSymbolAddress((void**)&rowmax, g_rowmax);
    cudaGetSymbolAddress((void**)&cand, g_cand);

    run_features(outputs, w, bi, A, B, featraw, rnorm, xn, xhh);
    run_features(styles,  w, bi, A, B, featraw, rnorm, sn, shh);

    dim3 mg(FEAT_N / 128, BATCH);
    maxdot_mma_kernel<<<mg, 256>>>(xhh, shh, cand);

    rescore_kernel<<<(BATCH * FEAT_N) / 8, 256>>>(xn, sn, cand, rowmax);
    loss_kernel<<<1, 256>>>(rowmax, (float*)d_out);
}

// round 7
// speedup vs baseline: 5.2364x; 3.6588x over previous
#include <cuda_runtime.h>
#include <cuda_fp16.h>
#include <math.h>
#include <stdint.h>

// ---------------------------------------------------------------------------
// Problem constants
// ---------------------------------------------------------------------------
#define BATCH 4
#define FEAT_C 768
#define FEAT_N 4096
#define EPS 1e-8f

// ---------------------------------------------------------------------------
// Device scratch (no allocations allowed). NHWC hi/lo fp16 activation planes.
// ---------------------------------------------------------------------------
#define ACT_ELEMS (BATCH * 256 * 256 * 64)   // 16.78M (biggest layer)
__device__ __align__(128) __half g_Ah[ACT_ELEMS];
__device__ __align__(128) __half g_Al[ACT_ELEMS];
__device__ __align__(128) __half g_Bh[ACT_ELEMS];
__device__ __align__(128) __half g_Bl[ACT_ELEMS];
__device__ __align__(128) __half g_feath[BATCH * FEAT_N * FEAT_C];
__device__ __align__(128) __half g_featl[BATCH * FEAT_N * FEAT_C];
#define WPOOL_ELEMS 1732608
__device__ __align__(128) __half g_wh[WPOOL_ELEMS];
__device__ __align__(128) __half g_wl[WPOOL_ELEMS];
__device__ __align__(128) float  g_xn[BATCH * FEAT_N * FEAT_C];
__device__ __align__(128) float  g_sn[BATCH * FEAT_N * FEAT_C];
__device__ __align__(128) __half g_xh[BATCH * FEAT_N * FEAT_C];
__device__ __align__(128) __half g_sh[BATCH * FEAT_N * FEAT_C];
__device__ float g_rnorm[BATCH * FEAT_N];
__device__ float g_rowmax[BATCH * FEAT_N];
__device__ int2  g_cand[BATCH * FEAT_N];

// Weight pool offsets: [tap][oc][ic] fp16 hi/lo per layer
#define W12_OFF 0         // 64x64
#define W21_OFF 36864     // 128x64
#define W22_OFF 110592    // 128x128
#define W31_OFF 258048    // 256x128
#define W32_OFF 552960    // 256x256
#define W33_OFF 1142784   // 256x256

// ---------------------------------------------------------------------------
// mma.sync helpers (verified in maxdot)
// ---------------------------------------------------------------------------
__device__ __forceinline__ uint32_t smem_addr32(const void* p) {
    return (uint32_t)__cvta_generic_to_shared(p);
}
__device__ __forceinline__ void ldm_x4(uint32_t addr, uint32_t r[4]) {
    asm volatile("ldmatrix.sync.aligned.m8n8.x4.shared.b16 {%0,%1,%2,%3}, [%4];"
                 : "=r"(r[0]), "=r"(r[1]), "=r"(r[2]), "=r"(r[3]) : "r"(addr));
}
__device__ __forceinline__ void mma16816(float d[4], const uint32_t a[4],
                                         uint32_t b0, uint32_t b1) {
    asm volatile(
        "mma.sync.aligned.m16n8k16.row.col.f32.f16.f16.f32 "
        "{%0,%1,%2,%3}, {%4,%5,%6,%7}, {%8,%9}, {%0,%1,%2,%3};"
        : "+f"(d[0]), "+f"(d[1]), "+f"(d[2]), "+f"(d[3])
        : "r"(a[0]), "r"(a[1]), "r"(a[2]), "r"(a[3]), "r"(b0), "r"(b1));
}

// ---------------------------------------------------------------------------
// Weight prep: fp32 OIHW -> hi/lo fp16 [tap][oc][ic]
// ---------------------------------------------------------------------------
__global__ void wprep_kernel(const float* __restrict__ w, __half* __restrict__ wh,
                             __half* __restrict__ wl, int Cout, int Cin) {
    int total = Cout * Cin * 9;
    for (int i = blockIdx.x * blockDim.x + threadIdx.x; i < total;
         i += gridDim.x * blockDim.x) {
        int oc = i / (Cin * 9);
        int r = i - oc * Cin * 9;
        int ic = r / 9;
        int k = r - ic * 9;
        float v = w[i];
        __half h = __float2half(v);
        __half l = __float2half(v - __half2float(h));
        int dst = k * Cout * Cin + oc * Cin + ic;
        wh[dst] = h;
        wl[dst] = l;
    }
}

// ---------------------------------------------------------------------------
// conv1_1: fused normalize + 3->64 conv + bias + relu, scalar fp32,
// reads NCHW input, writes NHWC hi/lo (stride 64)
// ---------------------------------------------------------------------------
__global__ __launch_bounds__(256)
void conv1_kernel(const float* __restrict__ img, const float* __restrict__ w,
                  const float* __restrict__ bias,
                  __half* __restrict__ oh, __half* __restrict__ ol) {
    __shared__ float sw[64 * 27];
    __shared__ float sb[64];
    int tid = threadIdx.x;
    for (int i = tid; i < 64 * 27; i += 256) sw[i] = w[i];
    if (tid < 64) sb[tid] = bias[tid];
    __syncthreads();

    const float mean[3] = {0.485f, 0.456f, 0.406f};
    const float istd[3] = {1.f / 0.229f, 1.f / 0.224f, 1.f / 0.225f};

    int gid = blockIdx.x * 256 + tid;   // pixel id over 4*65536
    int b = gid >> 16;
    int y = (gid >> 8) & 255;
    int x = gid & 255;

    float in[3][9];
#pragma unroll
    for (int c = 0; c < 3; c++) {
        const float* ip = img + (((long)b * 3 + c) << 16);
#pragma unroll
        for (int dy = 0; dy < 3; dy++)
#pragma unroll
            for (int dx = 0; dx < 3; dx++) {
                int gy = y + dy - 1, gx = x + dx - 1;
                float v = 0.f;
                if (gy >= 0 && gy < 256 && gx >= 0 && gx < 256)
                    v = (ip[(gy << 8) + gx] - mean[c]) * istd[c];
                in[c][dy * 3 + dx] = v;
            }
    }

    long obase = (long)gid * 64;
#pragma unroll 4
    for (int oc = 0; oc < 64; oc++) {
        float acc = sb[oc];
        const float* wp = &sw[oc * 27];
#pragma unroll
        for (int c = 0; c < 3; c++)
#pragma unroll
            for (int k = 0; k < 9; k++)
                acc = fmaf(in[c][k], wp[c * 9 + k], acc);
        acc = acc > 0.f ? acc : 0.f;
        __half h = __float2half(acc);
        oh[obase + oc] = h;
        ol[obase + oc] = __float2half(acc - __half2float(h));
    }
}

// ---------------------------------------------------------------------------
// Tensor-core 3x3 conv (9 shifted GEMMs), split-fp16 (hh+hl+lh), NHWC hi/lo.
// Block: 256 thr (8 warps). Tile: 8x16 px patch x 64 oc. k-chunk = 16 ic.
// ---------------------------------------------------------------------------
#define PATCH_H 8
#define PATCH_W 16
#define HALO_W 18
#define HALO_PX 180
#define SPAD 24
#define CONV_SMEM ((HALO_PX * SPAD * 2 + 9 * 64 * SPAD * 2) * 2)   // 72576 B

__global__ __launch_bounds__(256)
void conv_mma_kernel(const __half* __restrict__ inh, const __half* __restrict__ inl,
                     const __half* __restrict__ wh, const __half* __restrict__ wl,
                     const float* __restrict__ bias,
                     __half* __restrict__ outh, __half* __restrict__ outl,
                     int Cin, int Cout, int H, int W,
                     int inStride, int outStride) {
    extern __shared__ __half smem[];
    __half* sAh = smem;                       // [180][24]
    __half* sAl = sAh + HALO_PX * SPAD;       // +4320
    __half* sWh = sAl + HALO_PX * SPAD;       // [9][64][24]
    __half* sWl = sWh + 9 * 64 * SPAD;

    int tid = threadIdx.x;
    int lane = tid & 31;
    int wid = tid >> 5;
    int wn = wid & 3;      // pixel group: patch rows 2wn, 2wn+1
    int wm = wid >> 2;     // oc half (32 each)

    int ocb = Cout >> 6;
    int b = blockIdx.z / ocb;
    int oc0 = (blockIdx.z % ocb) << 6;
    int py0 = blockIdx.y * PATCH_H - 1;
    int px0 = blockIdx.x * PATCH_W - 1;

    int a_col8 = (lane >> 4) * 8;
    int a_row = lane & 15;
    int b_row = (lane & 7) + ((lane >> 4) * 8);
    int b_col8 = ((lane >> 3) & 1) * 8;

    float d[2][4][4];
#pragma unroll
    for (int i = 0; i < 2; i++)
#pragma unroll
        for (int j = 0; j < 4; j++)
#pragma unroll
            for (int e = 0; e < 4; e++) d[i][j][e] = 0.f;

    for (int icc = 0; icc < Cin; icc += 16) {
        // stage halo A patch: 180 px x 16 ic, hi+lo
        for (int u = tid; u < 360; u += 256) {
            int px = u >> 1;
            int v8 = (u & 1) << 3;
            int r = px / HALO_W;
            int c = px - r * HALO_W;
            int gy = py0 + r, gx = px0 + c;
            uint4 vh = make_uint4(0, 0, 0, 0), vl = make_uint4(0, 0, 0, 0);
            if (gy >= 0 && gy < H && gx >= 0 && gx < W) {
                long base = ((long)(b * H + gy) * W + gx) * inStride + icc + v8;
                vh = *(const uint4*)(inh + base);
                vl = *(const uint4*)(inl + base);
            }
            *(uint4*)&sAh[px * SPAD + v8] = vh;
            *(uint4*)&sAl[px * SPAD + v8] = vl;
        }
        // stage weights: 9 taps x 64 oc x 16 ic, hi+lo
        for (int u = tid; u < 1152; u += 256) {
            int v8 = (u & 1) << 3;
            int t = u >> 1;
            int tap = t >> 6;
            int oc = t & 63;
            long base = (long)tap * Cout * Cin + (long)(oc0 + oc) * Cin + icc + v8;
            *(uint4*)&sWh[(tap * 64 + oc) * SPAD + v8] = *(const uint4*)(wh + base);
            *(uint4*)&sWl[(tap * 64 + oc) * SPAD + v8] = *(const uint4*)(wl + base);
        }
        __syncthreads();

        for (int tap = 0; tap < 9; tap++) {
            int ky = tap / 3, kx = tap - ky * 3;
            uint32_t bfh[2][4], bfl[2][4];
#pragma unroll
            for (int p = 0; p < 2; p++) {
                int wrow = (tap * 64 + wm * 32 + p * 16 + b_row) * SPAD + b_col8;
                ldm_x4(smem_addr32(&sWh[wrow]), bfh[p]);
                ldm_x4(smem_addr32(&sWl[wrow]), bfl[p]);
            }
#pragma unroll
            for (int ar = 0; ar < 2; ar++) {
                int pr = wn * 2 + ar;
                int sidx = ((pr + ky) * HALO_W + kx + a_row) * SPAD + a_col8;
                uint32_t afh[4], afl[4];
                ldm_x4(smem_addr32(&sAh[sidx]), afh);
                ldm_x4(smem_addr32(&sAl[sidx]), afl);
#pragma unroll
                for (int p = 0; p < 2; p++) {
                    mma16816(d[ar][2 * p],     afh, bfh[p][0], bfh[p][1]);
                    mma16816(d[ar][2 * p + 1], afh, bfh[p][2], bfh[p][3]);
                    mma16816(d[ar][2 * p],     afh, bfl[p][0], bfl[p][1]);
                    mma16816(d[ar][2 * p + 1], afh, bfl[p][2], bfl[p][3]);
                    mma16816(d[ar][2 * p],     afl, bfh[p][0], bfh[p][1]);
                    mma16816(d[ar][2 * p + 1], afl, bfh[p][2], bfh[p][3]);
                }
            }
        }
        __syncthreads();
    }

    // epilogue: bias + relu + hi/lo split, NHWC half2 stores
    int obase_oc = oc0 + wm * 32 + (lane & 3) * 2;
    float2 bv[4];
#pragma unroll
    for (int nf = 0; nf < 4; nf++)
        bv[nf] = *(const float2*)(bias + obase_oc + nf * 8);

#pragma unroll
    for (int ar = 0; ar < 2; ar++) {
        int gy = blockIdx.y * PATCH_H + wn * 2 + ar;
#pragma unroll
        for (int eh = 0; eh < 2; eh++) {
            int gx = blockIdx.x * PATCH_W + (lane >> 2) + eh * 8;
            long pbase = ((long)(b * H + gy) * W + gx) * outStride;
#pragma unroll
            for (int nf = 0; nf < 4; nf++) {
                float v0 = d[ar][nf][eh * 2 + 0] + bv[nf].x;
                float v1 = d[ar][nf][eh * 2 + 1] + bv[nf].y;
                v0 = v0 > 0.f ? v0 : 0.f;
                v1 = v1 > 0.f ? v1 : 0.f;
                __half h0 = __float2half(v0);
                __half h1 = __float2half(v1);
                __half l0 = __float2half(v0 - __half2float(h0));
                __half l1 = __float2half(v1 - __half2float(h1));
                long oadr = pbase + obase_oc + nf * 8;
                *(__half2*)(outh + oadr) = __halves2half2(h0, h1);
                *(__half2*)(outl + oadr) = __halves2half2(l0, l1);
            }
        }
    }
}

// ---------------------------------------------------------------------------
// 2x2 maxpool on NHWC hi/lo planes (half2-vectorized over channels)
// ---------------------------------------------------------------------------
__global__ void maxpool_hl_kernel(const __half* __restrict__ ih, const __half* __restrict__ il,
                                  __half* __restrict__ oh, __half* __restrict__ ol,
                                  int C, int Hi, int Wi) {
    int Ho = Hi >> 1, Wo = Wi >> 1;
    int C2 = C >> 1;
    long total = (long)BATCH * Ho * Wo * C2;
    for (long i = blockIdx.x * (long)blockDim.x + threadIdx.x; i < total;
         i += (long)gridDim.x * blockDim.x) {
        int c2 = (int)(i % C2);
        long p = i / C2;
        int x = (int)(p % Wo);
        long t = p / Wo;
        int y = (int)(t % Ho);
        int b = (int)(t / Ho);
        float m0 = -1e30f, m1 = -1e30f;
#pragma unroll
        for (int dy = 0; dy < 2; dy++)
#pragma unroll
            for (int dx = 0; dx < 2; dx++) {
                long base = ((long)(b * Hi + 2 * y + dy) * Wi + 2 * x + dx) * C + c2 * 2;
                float2 h = __half22float2(*(const __half2*)(ih + base));
                float2 l = __half22float2(*(const __half2*)(il + base));
                float v0 = h.x + l.x, v1 = h.y + l.y;
                m0 = fmaxf(m0, v0);
                m1 = fmaxf(m1, v1);
            }
        long obase = ((long)(b * Ho + y) * Wo + x) * C + c2 * 2;
        __half h0 = __float2half(m0), h1 = __float2half(m1);
        *(__half2*)(oh + obase) = __halves2half2(h0, h1);
        *(__half2*)(ol + obase) = __halves2half2(__float2half(m0 - __half2float(h0)),
                                                 __float2half(m1 - __half2float(h1)));
    }
}

// ---------------------------------------------------------------------------
// Row norms of NHWC features (hi+lo): warp per row of 768
// ---------------------------------------------------------------------------
__global__ void norms_nhwc_kernel(const __half* __restrict__ fh, const __half* __restrict__ fl,
                                  float* __restrict__ rnorm) {
    int row = (blockIdx.x * blockDim.x + threadIdx.x) >> 5;
    int lane = threadIdx.x & 31;
    if (row >= BATCH * FEAT_N) return;
    const __half2* ph = (const __half2*)(fh + (long)row * FEAT_C);
    const __half2* pl = (const __half2*)(fl + (long)row * FEAT_C);
    float s = 0.f;
#pragma unroll
    for (int j = 0; j < 12; j++) {
        int k = j * 32 + lane;
        float2 h = __half22float2(ph[k]);
        float2 l = __half22float2(pl[k]);
        float v0 = h.x + l.x, v1 = h.y + l.y;
        s = fmaf(v0, v0, fmaf(v1, v1, s));
    }
#pragma unroll
    for (int off = 16; off > 0; off >>= 1) s += __shfl_xor_sync(0xFFFFFFFF, s, off);
    if (lane == 0) rnorm[row] = 1.f / (sqrtf(s) + EPS);
}

// ---------------------------------------------------------------------------
// Normalize: feat hi/lo -> fp32 (rescore) + fp16 (maxdot)
// ---------------------------------------------------------------------------
__global__ void normalize_kernel(const __half* __restrict__ fh, const __half* __restrict__ fl,
                                 const float* __restrict__ rnorm,
                                 float* __restrict__ xn, __half* __restrict__ xh) {
    long total = (long)BATCH * FEAT_N * (FEAT_C / 2);
    for (long i = blockIdx.x * (long)blockDim.x + threadIdx.x; i < total;
         i += (long)gridDim.x * blockDim.x) {
        long r = i / (FEAT_C / 2);
        float rn = rnorm[r];
        float2 h = __half22float2(*(const __half2*)(fh + i * 2));
        float2 l = __half22float2(*(const __half2*)(fl + i * 2));
        float v0 = (h.x + l.x) * rn;
        float v1 = (h.y + l.y) * rn;
        *(float2*)(xn + i * 2) = make_float2(v0, v1);
        *(__half2*)(xh + i * 2) = __halves2half2(__float2half(v0), __float2half(v1));
    }
}

// ---------------------------------------------------------------------------
// HMMA candidate search (unchanged from R6 — verified)
// ---------------------------------------------------------------------------
__device__ __forceinline__ void merge_top2(float& a1, int& ai1, float& a2, int& ai2,
                                           float b1, int bi1, float b2, int bi2) {
    if (b1 > a1) {
        float tv = a1; int ti = ai1;
        a1 = b1; ai1 = bi1;
        b1 = tv; bi1 = ti;
        if (b2 > a2) { a2 = b2; ai2 = bi2; }
    }
    if (b1 > a2) { a2 = b1; ai2 = bi1; }
}

#define MM_PAD 40

__global__ __launch_bounds__(256)
void maxdot_mma_kernel(const __half* __restrict__ xh, const __half* __restrict__ sh,
                       int2* __restrict__ cand) {
    __shared__ __half sA[128][MM_PAD];
    __shared__ __half sB[128][MM_PAD];
    __shared__ float sVal[128][4];
    __shared__ int   sIdx[128][4];

    int tid = threadIdx.x;
    int lane = tid & 31;
    int wid = tid >> 5;
    int wn = wid & 3;
    int wm = wid >> 2;
    int b = blockIdx.y;
    int n0 = blockIdx.x * 128;

    float t1[4], t2[4];
    int i1[4], i2[4];
#pragma unroll
    for (int s = 0; s < 4; s++) { t1[s] = -1e30f; t2[s] = -1e30f; i1[s] = 0; i2[s] = 0; }

    int ldrow = tid >> 1;
    int ldseg = tid & 1;
    const __half* xrow = xh + ((long)(b * FEAT_N + n0 + ldrow)) * FEAT_C + ldseg * 16;

    int a_row = (lane & 15);
    int a_col8 = (lane >> 4) * 8;
    int b_row = (lane & 7) + ((lane >> 4) * 8);
    int b_col8 = ((lane >> 3) & 1) * 8;

    for (int mt = 0; mt < 32; mt++) {
        float d[2][8][4];
#pragma unroll
        for (int mf = 0; mf < 2; mf++)
#pragma unroll
            for (int nf = 0; nf < 8; nf++)
#pragma unroll
                for (int e = 0; e < 4; e++) d[mf][nf][e] = 0.f;

        const __half* srow = sh + ((long)(b * FEAT_N + mt * 128 + ldrow)) * FEAT_C + ldseg * 16;

        for (int kc = 0; kc < 24; kc++) {
            const uint4* xp = (const uint4*)(xrow + kc * 32);
            const uint4* spp = (const uint4*)(srow + kc * 32);
            uint4 va0 = xp[0], va1 = xp[1];
            uint4 vb0 = spp[0], vb1 = spp[1];
            *(uint4*)&sA[ldrow][ldseg * 16] = va0;
            *(uint4*)&sA[ldrow][ldseg * 16 + 8] = va1;
            *(uint4*)&sB[ldrow][ldseg * 16] = vb0;
            *(uint4*)&sB[ldrow][ldseg * 16 + 8] = vb1;
            __syncthreads();

#pragma unroll
            for (int ks = 0; ks < 2; ks++) {
                uint32_t bf[4][4];
#pragma unroll
                for (int p = 0; p < 4; p++) {
                    uint32_t ad = smem_addr32(&sB[wm * 64 + p * 16 + b_row][ks * 16 + b_col8]);
                    ldm_x4(ad, bf[p]);
                }
#pragma unroll
                for (int mf = 0; mf < 2; mf++) {
                    uint32_t af[4];
                    uint32_t ad = smem_addr32(&sA[wn * 32 + mf * 16 + a_row][ks * 16 + a_col8]);
                    ldm_x4(ad, af);
#pragma unroll
                    for (int p = 0; p < 4; p++) {
                        mma16816(d[mf][2 * p],     af, bf[p][0], bf[p][1]);
                        mma16816(d[mf][2 * p + 1], af, bf[p][2], bf[p][3]);
                    }
                }
            }
            __syncthreads();
        }

#pragma unroll
        for (int mf = 0; mf < 2; mf++)
#pragma unroll
            for (int nf = 0; nf < 8; nf++) {
                int colb = mt * 128 + wm * 64 + nf * 8 + (lane & 3) * 2;
#pragma unroll
                for (int e = 0; e < 4; e++) {
                    int s = mf * 2 + (e >> 1);
                    float v = d[mf][nf][e];
                    int m = colb + (e & 1);
                    if (v > t1[s]) { t2[s] = t1[s]; i2[s] = i1[s]; t1[s] = v; i1[s] = m; }
                    else if (v > t2[s]) { t2[s] = v; i2[s] = m; }
                }
            }
    }

#pragma unroll
    for (int off = 1; off <= 2; off <<= 1) {
#pragma unroll
        for (int s = 0; s < 4; s++) {
            float o1 = __shfl_xor_sync(0xFFFFFFFF, t1[s], off);
            float o2 = __shfl_xor_sync(0xFFFFFFFF, t2[s], off);
            int oi1 = __shfl_xor_sync(0xFFFFFFFF, i1[s], off);
            int oi2 = __shfl_xor_sync(0xFFFFFFFF, i2[s], off);
            merge_top2(t1[s], i1[s], t2[s], i2[s], o1, oi1, o2, oi2);
        }
    }

    if ((lane & 3) == 0) {
#pragma unroll
        for (int s = 0; s < 4; s++) {
            int mf = s >> 1;
            int hi = s & 1;
            int row = wn * 32 + mf * 16 + (lane >> 2) + hi * 8;
            sVal[row][wm * 2 + 0] = t1[s];
            sVal[row][wm * 2 + 1] = t2[s];
            sIdx[row][wm * 2 + 0] = i1[s];
            sIdx[row][wm * 2 + 1] = i2[s];
        }
    }
    __syncthreads();

    if (tid < 128) {
        float a1 = sVal[tid][0], a2 = sVal[tid][1];
        int ai1 = sIdx[tid][0], ai2 = sIdx[tid][1];
        merge_top2(a1, ai1, a2, ai2, sVal[tid][2], sIdx[tid][2], sVal[tid][3], sIdx[tid][3]);
        cand[b * FEAT_N + n0 + tid] = make_int2(ai1, ai2);
    }
}

// ---------------------------------------------------------------------------
// Exact fp32 rescore + final reduction (unchanged)
// ---------------------------------------------------------------------------
__global__ void rescore_kernel(const float* __restrict__ xn, const float* __restrict__ sn,
                               const int2* __restrict__ cand, float* __restrict__ rowmax) {
    int gwarp = (blockIdx.x * blockDim.x + threadIdx.x) >> 5;
    int lane = threadIdx.x & 31;
    if (gwarp >= BATCH * FEAT_N) return;
    int b = gwarp >> 12;
    int2 c = cand[gwarp];
    const float4* xr = (const float4*)(xn + (long)gwarp * FEAT_C);
    const float4* s1 = (const float4*)(sn + ((long)(b << 12) + c.x) * FEAT_C);
    const float4* s2 = (const float4*)(sn + ((long)(b << 12) + c.y) * FEAT_C);
    float d1 = 0.f, d2 = 0.f;
#pragma unroll
    for (int i = 0; i < 6; i++) {
        int k = i * 32 + lane;
        float4 xv = xr[k], a = s1[k], bb = s2[k];
        d1 += xv.x * a.x + xv.y * a.y + xv.z * a.z + xv.w * a.w;
        d2 += xv.x * bb.x + xv.y * bb.y + xv.z * bb.z + xv.w * bb.w;
    }
#pragma unroll
    for (int off = 16; off > 0; off >>= 1) {
        d1 += __shfl_xor_sync(0xFFFFFFFF, d1, off);
        d2 += __shfl_xor_sync(0xFFFFFFFF, d2, off);
    }
    if (lane == 0) rowmax[gwarp] = fmaxf(d1, d2);
}

__global__ void loss_kernel(const float* __restrict__ rowmax, float* __restrict__ out) {
    __shared__ float sred[256];
    float s = 0.f;
    for (int i = threadIdx.x; i < BATCH * FEAT_N; i += 256)
        s += 1.0f - rowmax[i];
    sred[threadIdx.x] = s;
    __syncthreads();
    for (int k = 128; k > 0; k >>= 1) {
        if (threadIdx.x < k) sred[threadIdx.x] += sred[threadIdx.x + k];
        __syncthreads();
    }
    if (threadIdx.x == 0) out[0] = sred[0] / (float)(BATCH * FEAT_N);
}

// ---------------------------------------------------------------------------
// Host orchestration
// ---------------------------------------------------------------------------
static void launch_conv_mma(const __half* ih, const __half* il,
                            const __half* wh, const __half* wl, const float* bias,
                            __half* oh, __half* ol,
                            int Cin, int Cout, int H, int W, int inStride, int outStride) {
    dim3 grid(W / PATCH_W, H / PATCH_H, BATCH * (Cout / 64));
    conv_mma_kernel<<<grid, 256, CONV_SMEM>>>(ih, il, wh, wl, bias, oh, ol,
                                              Cin, Cout, H, W, inStride, outStride);
}

static void run_features(const float* img, const float* const* w, const float* const* bi,
                         __half* Ah, __half* Al, __half* Bh, __half* Bl,
                         __half* fh, __half* fl, const __half* wh, const __half* wl,
                         float* rnorm, float* xn, __half* xh) {
    conv1_kernel<<<BATCH * 65536 / 256, 256>>>(img, w[0], bi[0], Ah, Al);
    launch_conv_mma(Ah, Al, wh + W12_OFF, wl + W12_OFF, bi[1], Bh, Bl,
                    64, 64, 256, 256, 64, 64);
    maxpool_hl_kernel<<<2048, 256>>>(Bh, Bl, Ah, Al, 64, 256, 256);
    launch_conv_mma(Ah, Al, wh + W21_OFF, wl + W21_OFF, bi[2], Bh, Bl,
                    64, 128, 128, 128, 64, 128);
    launch_conv_mma(Bh, Bl, wh + W22_OFF, wl + W22_OFF, bi[3], Ah, Al,
                    128, 128, 128, 128, 128, 128);
    maxpool_hl_kernel<<<1024, 256>>>(Ah, Al, Bh, Bl, 128, 128, 128);
    launch_conv_mma(Bh, Bl, wh + W31_OFF, wl + W31_OFF, bi[4], fh, fl,
                    128, 256, 64, 64, 128, 768);
    launch_conv_mma(fh, fl, wh + W32_OFF, wl + W32_OFF, bi[5], fh + 256, fl + 256,
                    256, 256, 64, 64, 768, 768);
    launch_conv_mma(fh + 256, fl + 256, wh + W33_OFF, wl + W33_OFF, bi[6],
                    fh + 512, fl + 512, 256, 256, 64, 64, 768, 768);
    norms_nhwc_kernel<<<(BATCH * FEAT_N * 32 + 255) / 256, 256>>>(fh, fl, rnorm);
    normalize_kernel<<<2048, 256>>>(fh, fl, rnorm, xn, xh);
}

extern "C" void kernel_launch(void* const* d_in, const int* in_sizes, int n_in,
                              void* d_out, int out_size) {
    const float* outputs = (const float*)d_in[0];
    const float* styles  = (const float*)d_in[1];
    const float* w[7];
    const float* bi[7];
    for (int i = 0; i < 7; i++) {
        w[i]  = (const float*)d_in[2 + 2 * i];
        bi[i] = (const float*)d_in[3 + 2 * i];
    }

    __half *Ah, *Al, *Bh, *Bl, *fh, *fl, *wh, *wl, *xhh, *shh;
    float *xn, *sn, *rnorm, *rowmax;
    int2* cand;
    cudaGetSymbolAddress((void**)&Ah, g_Ah);
    cudaGetSymbolAddress((void**)&Al, g_Al);
    cudaGetSymbolAddress((void**)&Bh, g_Bh);
    cudaGetSymbolAddress((void**)&Bl, g_Bl);
    cudaGetSymbolAddress((void**)&fh, g_feath);
    cudaGetSymbolAddress((void**)&fl, g_featl);
    cudaGetSymbolAddress((void**)&wh, g_wh);
    cudaGetSymbolAddress((void**)&wl, g_wl);
    cudaGetSymbolAddress((void**)&xn, g_xn);
    cudaGetSymbolAddress((void**)&sn, g_sn);
    cudaGetSymbolAddress((void**)&xhh, g_xh);
    cudaGetSymbolAddress((void**)&shh, g_sh);
    cudaGetSymbolAddress((void**)&rnorm, g_rnorm);
    cudaGetSymbolAddress((void**)&rowmax, g_rowmax);
    cudaGetSymbolAddress((void**)&cand, g_cand);

    cudaFuncSetAttribute(conv_mma_kernel, cudaFuncAttributeMaxDynamicSharedMemorySize,
                         CONV_SMEM);

    // weight prep (tiny)
    wprep_kernel<<<144, 256>>>(w[1], wh + W12_OFF, wl + W12_OFF, 64, 64);
    wprep_kernel<<<288, 256>>>(w[2], wh + W21_OFF, wl + W21_OFF, 128, 64);
    wprep_kernel<<<576, 256>>>(w[3], wh + W22_OFF, wl + W22_OFF, 128, 128);
    wprep_kernel<<<1152, 256>>>(w[4], wh + W31_OFF, wl + W31_OFF, 256, 128);
    wprep_kernel<<<2304, 256>>>(w[5], wh + W32_OFF, wl + W32_OFF, 256, 256);
    wprep_kernel<<<2304, 256>>>(w[6], wh + W33_OFF, wl + W33_OFF, 256, 256);

    run_features(outputs, w, bi, Ah, Al, Bh, Bl, fh, fl, wh, wl, rnorm, xn, xhh);
    run_features(styles,  w, bi, Ah, Al, Bh, Bl, fh, fl, wh, wl, rnorm, sn, shh);

    dim3 mg(FEAT_N / 128, BATCH);
    maxdot_mma_kernel<<<mg, 256>>>(xhh, shh, cand);
    rescore_kernel<<<(BATCH * FEAT_N) / 8, 256>>>(xn, sn, cand, rowmax);
    loss_kernel<<<1, 256>>>(rowmax, (float*)d_out);
}

// round 8
// speedup vs baseline: 5.9174x; 1.1301x over previous
#include <cuda_runtime.h>
#include <cuda_fp16.h>
#include <math.h>
#include <stdint.h>

// ---------------------------------------------------------------------------
// Problem constants
// ---------------------------------------------------------------------------
#define BATCH 4
#define NBATCH 8            // outputs(0-3) + styles(4-7) fused
#define FEAT_C 768
#define FEAT_N 4096
#define EPS 1e-8f

// ---------------------------------------------------------------------------
// Device scratch (no allocations allowed). NHWC hi/lo fp16 activation planes.
// ---------------------------------------------------------------------------
#define ACT_ELEMS (NBATCH * 256 * 256 * 64)
__device__ __align__(128) __half g_Ah[ACT_ELEMS];
__device__ __align__(128) __half g_Al[ACT_ELEMS];
__device__ __align__(128) __half g_Bh[ACT_ELEMS];
__device__ __align__(128) __half g_Bl[ACT_ELEMS];
__device__ __align__(128) __half g_feath[NBATCH * FEAT_N * FEAT_C];
__device__ __align__(128) __half g_featl[NBATCH * FEAT_N * FEAT_C];
#define WPOOL_ELEMS 1732608
__device__ __align__(128) __half g_wh[WPOOL_ELEMS];
__device__ __align__(128) __half g_wl[WPOOL_ELEMS];
__device__ __align__(128) float  g_xn[NBATCH * FEAT_N * FEAT_C];
__device__ __align__(128) __half g_xh[NBATCH * FEAT_N * FEAT_C];
__device__ float g_rnorm[NBATCH * FEAT_N];
__device__ float g_rowmax[BATCH * FEAT_N];
__device__ int2  g_cand[BATCH * FEAT_N];

// Weight pool offsets (halves; fragment-permuted within each layer block)
#define W12_OFF 0         // 64x64
#define W21_OFF 36864     // 128x64
#define W22_OFF 110592    // 128x128
#define W31_OFF 258048    // 256x128
#define W32_OFF 552960    // 256x256
#define W33_OFF 1142784   // 256x256

// ---------------------------------------------------------------------------
// mma.sync helpers (verified)
// ---------------------------------------------------------------------------
__device__ __forceinline__ uint32_t smem_addr32(const void* p) {
    return (uint32_t)__cvta_generic_to_shared(p);
}
__device__ __forceinline__ void ldm_x4(uint32_t addr, uint32_t r[4]) {
    asm volatile("ldmatrix.sync.aligned.m8n8.x4.shared.b16 {%0,%1,%2,%3}, [%4];"
                 : "=r"(r[0]), "=r"(r[1]), "=r"(r[2]), "=r"(r[3]) : "r"(addr));
}
__device__ __forceinline__ void mma16816(float d[4], const uint32_t a[4],
                                         uint32_t b0, uint32_t b1) {
    asm volatile(
        "mma.sync.aligned.m16n8k16.row.col.f32.f16.f16.f32 "
        "{%0,%1,%2,%3}, {%4,%5,%6,%7}, {%8,%9}, {%0,%1,%2,%3};"
        : "+f"(d[0]), "+f"(d[1]), "+f"(d[2]), "+f"(d[3])
        : "r"(a[0]), "r"(a[1]), "r"(a[2]), "r"(a[3]), "r"(b0), "r"(b1));
}
__device__ __forceinline__ void cp_async16(uint32_t saddr, const void* gaddr, int srcsz) {
    asm volatile("cp.async.ca.shared.global [%0], [%1], 16, %2;"
                 :: "r"(saddr), "l"(gaddr), "r"(srcsz));
}

// ---------------------------------------------------------------------------
// Weight prep: fp32 OIHW -> hi/lo fp16 fragment-ordered tiles
// tile = (tap*(Co/16) + oc16)*(Ci/16) + kc ; 128 u32 per tile = [lane][reg j]
// reg j, lane l -> oc = oc16*16 + (j>>1)*8 + l/4 ; ic = kc*16 + (j&1)*8 + 2*(l%4)
// ---------------------------------------------------------------------------
__global__ void wprep_frag_kernel(const float* __restrict__ w, __half* __restrict__ wh,
                                  __half* __restrict__ wl, int Cout, int Cin) {
    uint32_t* whu = (uint32_t*)wh;
    uint32_t* wlu = (uint32_t*)wl;
    int ci16 = Cin >> 4, co16 = Cout >> 4;
    int total = 9 * co16 * ci16 * 128;
    for (int i = blockIdx.x * blockDim.x + threadIdx.x; i < total;
         i += gridDim.x * blockDim.x) {
        int tile = i >> 7;
        int r = i & 127;
        int lane = r >> 2, j = r & 3;
        int tap = tile / (co16 * ci16);
        int rem = tile - tap * co16 * ci16;
        int o16 = rem / ci16;
        int kc = rem - o16 * ci16;
        int oc = o16 * 16 + ((j >> 1) << 3) + (lane >> 2);
        int ic = kc * 16 + ((j & 1) << 3) + ((lane & 3) << 1);
        float v0 = w[((long)oc * Cin + ic) * 9 + tap];
        float v1 = w[((long)oc * Cin + ic + 1) * 9 + tap];
        __half h0 = __float2half(v0), h1 = __float2half(v1);
        __half l0 = __float2half(v0 - __half2float(h0));
        __half l1 = __float2half(v1 - __half2float(h1));
        __half2 hh = __halves2half2(h0, h1);
        __half2 ll = __halves2half2(l0, l1);
        whu[i] = *(uint32_t*)&hh;
        wlu[i] = *(uint32_t*)&ll;
    }
}

// ---------------------------------------------------------------------------
// conv1_1: fused normalize + 3->64 conv + bias + relu (batch 8, two sources)
// ---------------------------------------------------------------------------
__global__ __launch_bounds__(256)
void conv1_kernel(const float* __restrict__ imgA, const float* __restrict__ imgB,
                  const float* __restrict__ w, const float* __restrict__ bias,
                  __half* __restrict__ oh, __half* __restrict__ ol) {
    __shared__ float sw[64 * 27];
    __shared__ float sb[64];
    int tid = threadIdx.x;
    for (int i = tid; i < 64 * 27; i += 256) sw[i] = w[i];
    if (tid < 64) sb[tid] = bias[tid];
    __syncthreads();

    const float mean[3] = {0.485f, 0.456f, 0.406f};
    const float istd[3] = {1.f / 0.229f, 1.f / 0.224f, 1.f / 0.225f};

    int gid = blockIdx.x * 256 + tid;
    int b = gid >> 16;
    int y = (gid >> 8) & 255;
    int x = gid & 255;
    const float* base = (b < 4) ? imgA : imgB;
    int bb = b & 3;

    float in[3][9];
#pragma unroll
    for (int c = 0; c < 3; c++) {
        const float* ip = base + (((long)bb * 3 + c) << 16);
#pragma unroll
        for (int dy = 0; dy < 3; dy++)
#pragma unroll
            for (int dx = 0; dx < 3; dx++) {
                int gy = y + dy - 1, gx = x + dx - 1;
                float v = 0.f;
                if (gy >= 0 && gy < 256 && gx >= 0 && gx < 256)
                    v = (ip[(gy << 8) + gx] - mean[c]) * istd[c];
                in[c][dy * 3 + dx] = v;
            }
    }

    long obase = (long)gid * 64;
#pragma unroll 4
    for (int oc = 0; oc < 64; oc++) {
        float acc = sb[oc];
        const float* wp = &sw[oc * 27];
#pragma unroll
        for (int c = 0; c < 3; c++)
#pragma unroll
            for (int k = 0; k < 9; k++)
                acc = fmaf(in[c][k], wp[c * 9 + k], acc);
        acc = acc > 0.f ? acc : 0.f;
        __half h = __float2half(acc);
        oh[obase + oc] = h;
        ol[obase + oc] = __float2half(acc - __half2float(h));
    }
}

// ---------------------------------------------------------------------------
// Tensor-core 3x3 conv: 9 shifted GEMMs, split-fp16 (hh+hl+lh).
// Weights: fragment-ordered global loads (no smem). A: cp.async double buffer.
// Block 256 thr; tile 8x16 px x 64 oc; k-chunk 16 ic.
// ---------------------------------------------------------------------------
#define HALO_W 18
#define HALO_PX 180
#define SPAD 24
#define APLANE (HALO_PX * SPAD)     // 4320 halves per plane

__global__ __launch_bounds__(256)
void conv_mma_kernel(const __half* __restrict__ inh, const __half* __restrict__ inl,
                     const __half* __restrict__ wfh, const __half* __restrict__ wfl,
                     const float* __restrict__ bias,
                     __half* __restrict__ outh, __half* __restrict__ outl,
                     int Cin, int Cout, int H, int W,
                     int inStride, int outStride) {
    __shared__ __align__(16) __half smem[4 * APLANE];   // [buf][plane][180][24]
    uint32_t sb32 = smem_addr32(smem);

    int tid = threadIdx.x;
    int lane = tid & 31;
    int wid = tid >> 5;
    int wn = wid & 3;      // pixel row group
    int wm = wid >> 2;     // oc half (32 each)

    int ocb = Cout >> 6;
    int b = blockIdx.z / ocb;
    int oc0 = (blockIdx.z % ocb) << 6;
    int py0 = blockIdx.y * 8 - 1;
    int px0 = blockIdx.x * 16 - 1;

    int a_row = lane & 15;
    int a_col8 = (lane >> 4) * 8;
    int nk = Cin >> 4;
    int co16 = Cout >> 4, ci16 = Cin >> 4;
    const uint4* wfh4 = (const uint4*)wfh;
    const uint4* wfl4 = (const uint4*)wfl;

    float d[2][4][4];
#pragma unroll
    for (int i = 0; i < 2; i++)
#pragma unroll
        for (int j = 0; j < 4; j++)
#pragma unroll
            for (int e = 0; e < 4; e++) d[i][j][e] = 0.f;

    auto stage = [&](int kc, int buf) {
        int icc = kc << 4;
        for (int u = tid; u < 720; u += 256) {
            int plane = u >= 360;
            int idx = u - (plane ? 360 : 0);
            int px = idx >> 1, seg = idx & 1;
            int r = px / HALO_W, c = px - r * HALO_W;
            int gy = py0 + r, gx = px0 + c;
            int valid = (gy >= 0 && gy < H && gx >= 0 && gx < W) ? 16 : 0;
            int gyc = gy < 0 ? 0 : (gy >= H ? H - 1 : gy);
            int gxc = gx < 0 ? 0 : (gx >= W ? W - 1 : gx);
            const __half* gp = (plane ? inl : inh)
                + ((long)(b * H + gyc) * W + gxc) * inStride + icc + seg * 8;
            uint32_t sa = sb32 + ((buf * 2 + plane) * APLANE + px * SPAD + seg * 8) * 2;
            cp_async16(sa, gp, valid);
        }
        asm volatile("cp.async.commit_group;" ::: "memory");
    };

    stage(0, 0);

    for (int kc = 0; kc < nk; kc++) {
        int buf = kc & 1;
        if (kc + 1 < nk) {
            stage(kc + 1, buf ^ 1);
            asm volatile("cp.async.wait_group 1;" ::: "memory");
        } else {
            asm volatile("cp.async.wait_group 0;" ::: "memory");
        }
        __syncthreads();

        int tb = (oc0 >> 4) + wm * 2;
#pragma unroll 3
        for (int tap = 0; tap < 9; tap++) {
            int ky = tap / 3, kx = tap - ky * 3;
            uint32_t bfh[2][4], bfl[2][4];
#pragma unroll
            for (int p = 0; p < 2; p++) {
                long t = ((long)(tap * co16 + tb + p)) * ci16 + kc;
                uint4 vh = wfh4[t * 32 + lane];
                uint4 vl = wfl4[t * 32 + lane];
                bfh[p][0] = vh.x; bfh[p][1] = vh.y; bfh[p][2] = vh.z; bfh[p][3] = vh.w;
                bfl[p][0] = vl.x; bfl[p][1] = vl.y; bfl[p][2] = vl.z; bfl[p][3] = vl.w;
            }
#pragma unroll
            for (int ar = 0; ar < 2; ar++) {
                int pr = wn * 2 + ar;
                uint32_t offA = sb32
                    + ((buf * 2) * APLANE + ((pr + ky) * HALO_W + kx + a_row) * SPAD + a_col8) * 2;
                uint32_t afh[4], afl[4];
                ldm_x4(offA, afh);
                ldm_x4(offA + APLANE * 2, afl);
#pragma unroll
                for (int p = 0; p < 2; p++) {
                    mma16816(d[ar][2 * p],     afh, bfh[p][0], bfh[p][1]);
                    mma16816(d[ar][2 * p + 1], afh, bfh[p][2], bfh[p][3]);
                    mma16816(d[ar][2 * p],     afh, bfl[p][0], bfl[p][1]);
                    mma16816(d[ar][2 * p + 1], afh, bfl[p][2], bfl[p][3]);
                    mma16816(d[ar][2 * p],     afl, bfh[p][0], bfh[p][1]);
                    mma16816(d[ar][2 * p + 1], afl, bfh[p][2], bfh[p][3]);
                }
            }
        }
        __syncthreads();
    }

    // epilogue: bias + relu + hi/lo split
    int obase_oc = oc0 + wm * 32 + (lane & 3) * 2;
    float2 bv[4];
#pragma unroll
    for (int nf = 0; nf < 4; nf++)
        bv[nf] = *(const float2*)(bias + obase_oc + nf * 8);

#pragma unroll
    for (int ar = 0; ar < 2; ar++) {
        int gy = blockIdx.y * 8 + wn * 2 + ar;
#pragma unroll
        for (int eh = 0; eh < 2; eh++) {
            int gx = blockIdx.x * 16 + (lane >> 2) + eh * 8;
            long pbase = ((long)(b * H + gy) * W + gx) * outStride;
#pragma unroll
            for (int nf = 0; nf < 4; nf++) {
                float v0 = d[ar][nf][eh * 2 + 0] + bv[nf].x;
                float v1 = d[ar][nf][eh * 2 + 1] + bv[nf].y;
                v0 = v0 > 0.f ? v0 : 0.f;
                v1 = v1 > 0.f ? v1 : 0.f;
                __half h0 = __float2half(v0);
                __half h1 = __float2half(v1);
                __half l0 = __float2half(v0 - __half2float(h0));
                __half l1 = __float2half(v1 - __half2float(h1));
                long oadr = pbase + obase_oc + nf * 8;
                *(__half2*)(outh + oadr) = __halves2half2(h0, h1);
                *(__half2*)(outl + oadr) = __halves2half2(l0, l1);
            }
        }
    }
}

// ---------------------------------------------------------------------------
// 2x2 maxpool on NHWC hi/lo planes
// ---------------------------------------------------------------------------
__global__ void maxpool_hl_kernel(const __half* __restrict__ ih, const __half* __restrict__ il,
                                  __half* __restrict__ oh, __half* __restrict__ ol,
                                  int C, int Hi, int Wi, int nb) {
    int Ho = Hi >> 1, Wo = Wi >> 1;
    int C2 = C >> 1;
    long total = (long)nb * Ho * Wo * C2;
    for (long i = blockIdx.x * (long)blockDim.x + threadIdx.x; i < total;
         i += (long)gridDim.x * blockDim.x) {
        int c2 = (int)(i % C2);
        long p = i / C2;
        int x = (int)(p % Wo);
        long t = p / Wo;
        int y = (int)(t % Ho);
        int b = (int)(t / Ho);
        float m0 = -1e30f, m1 = -1e30f;
#pragma unroll
        for (int dy = 0; dy < 2; dy++)
#pragma unroll
            for (int dx = 0; dx < 2; dx++) {
                long base = ((long)(b * Hi + 2 * y + dy) * Wi + 2 * x + dx) * C + c2 * 2;
                float2 h = __half22float2(*(const __half2*)(ih + base));
                float2 l = __half22float2(*(const __half2*)(il + base));
                m0 = fmaxf(m0, h.x + l.x);
                m1 = fmaxf(m1, h.y + l.y);
            }
        long obase = ((long)(b * Ho + y) * Wo + x) * C + c2 * 2;
        __half h0 = __float2half(m0), h1 = __float2half(m1);
        *(__half2*)(oh + obase) = __halves2half2(h0, h1);
        *(__half2*)(ol + obase) = __halves2half2(__float2half(m0 - __half2float(h0)),
                                                 __float2half(m1 - __half2float(h1)));
    }
}

// ---------------------------------------------------------------------------
// Row norms (hi+lo), warp per 768-channel row
// ---------------------------------------------------------------------------
__global__ void norms_nhwc_kernel(const __half* __restrict__ fh, const __half* __restrict__ fl,
                                  float* __restrict__ rnorm) {
    int row = (blockIdx.x * blockDim.x + threadIdx.x) >> 5;
    int lane = threadIdx.x & 31;
    if (row >= NBATCH * FEAT_N) return;
    const __half2* ph = (const __half2*)(fh + (long)row * FEAT_C);
    const __half2* pl = (const __half2*)(fl + (long)row * FEAT_C);
    float s = 0.f;
#pragma unroll
    for (int j = 0; j < 12; j++) {
        int k = j * 32 + lane;
        float2 h = __half22float2(ph[k]);
        float2 l = __half22float2(pl[k]);
        float v0 = h.x + l.x, v1 = h.y + l.y;
        s = fmaf(v0, v0, fmaf(v1, v1, s));
    }
#pragma unroll
    for (int off = 16; off > 0; off >>= 1) s += __shfl_xor_sync(0xFFFFFFFF, s, off);
    if (lane == 0) rnorm[row] = 1.f / (sqrtf(s) + EPS);
}

// ---------------------------------------------------------------------------
// Normalize: hi/lo -> fp32 + fp16
// ---------------------------------------------------------------------------
__global__ void normalize_kernel(const __half* __restrict__ fh, const __half* __restrict__ fl,
                                 const float* __restrict__ rnorm,
                                 float* __restrict__ xn, __half* __restrict__ xh) {
    long total = (long)NBATCH * FEAT_N * (FEAT_C / 2);
    for (long i = blockIdx.x * (long)blockDim.x + threadIdx.x; i < total;
         i += (long)gridDim.x * blockDim.x) {
        long r = i / (FEAT_C / 2);
        float rn = rnorm[r];
        float2 h = __half22float2(*(const __half2*)(fh + i * 2));
        float2 l = __half22float2(*(const __half2*)(fl + i * 2));
        float v0 = (h.x + l.x) * rn;
        float v1 = (h.y + l.y) * rn;
        *(float2*)(xn + i * 2) = make_float2(v0, v1);
        *(__half2*)(xh + i * 2) = __halves2half2(__float2half(v0), __float2half(v1));
    }
}

// ---------------------------------------------------------------------------
// HMMA candidate search (verified in R6/R7)
// ---------------------------------------------------------------------------
__device__ __forceinline__ void merge_top2(float& a1, int& ai1, float& a2, int& ai2,
                                           float b1, int bi1, float b2, int bi2) {
    if (b1 > a1) {
        float tv = a1; int ti = ai1;
        a1 = b1; ai1 = bi1;
        b1 = tv; bi1 = ti;
        if (b2 > a2) { a2 = b2; ai2 = bi2; }
    }
    if (b1 > a2) { a2 = b1; ai2 = bi1; }
}

#define MM_PAD 40

__global__ __launch_bounds__(256)
void maxdot_mma_kernel(const __half* __restrict__ xh, const __half* __restrict__ sh,
                       int2* __restrict__ cand) {
    __shared__ __half sA[128][MM_PAD];
    __shared__ __half sB[128][MM_PAD];
    __shared__ float sVal[128][4];
    __shared__ int   sIdx[128][4];

    int tid = threadIdx.x;
    int lane = tid & 31;
    int wid = tid >> 5;
    int wn = wid & 3;
    int wm = wid >> 2;
    int b = blockIdx.y;
    int n0 = blockIdx.x * 128;

    float t1[4], t2[4];
    int i1[4], i2[4];
#pragma unroll
    for (int s = 0; s < 4; s++) { t1[s] = -1e30f; t2[s] = -1e30f; i1[s] = 0; i2[s] = 0; }

    int ldrow = tid >> 1;
    int ldseg = tid & 1;
    const __half* xrow = xh + ((long)(b * FEAT_N + n0 + ldrow)) * FEAT_C + ldseg * 16;

    int a_row = (lane & 15);
    int a_col8 = (lane >> 4) * 8;
    int b_row = (lane & 7) + ((lane >> 4) * 8);
    int b_col8 = ((lane >> 3) & 1) * 8;

    for (int mt = 0; mt < 32; mt++) {
        float d[2][8][4];
#pragma unroll
        for (int mf = 0; mf < 2; mf++)
#pragma unroll
            for (int nf = 0; nf < 8; nf++)
#pragma unroll
                for (int e = 0; e < 4; e++) d[mf][nf][e] = 0.f;

        const __half* srow = sh + ((long)(b * FEAT_N + mt * 128 + ldrow)) * FEAT_C + ldseg * 16;

        for (int kc = 0; kc < 24; kc++) {
            const uint4* xp = (const uint4*)(xrow + kc * 32);
            const uint4* spp = (const uint4*)(srow + kc * 32);
            uint4 va0 = xp[0], va1 = xp[1];
            uint4 vb0 = spp[0], vb1 = spp[1];
            *(uint4*)&sA[ldrow][ldseg * 16] = va0;
            *(uint4*)&sA[ldrow][ldseg * 16 + 8] = va1;
            *(uint4*)&sB[ldrow][ldseg * 16] = vb0;
            *(uint4*)&sB[ldrow][ldseg * 16 + 8] = vb1;
            __syncthreads();

#pragma unroll
            for (int ks = 0; ks < 2; ks++) {
                uint32_t bf[4][4];
#pragma unroll
                for (int p = 0; p < 4; p++) {
                    uint32_t ad = smem_addr32(&sB[wm * 64 + p * 16 + b_row][ks * 16 + b_col8]);
                    ldm_x4(ad, bf[p]);
                }
#pragma unroll
                for (int mf = 0; mf < 2; mf++) {
                    uint32_t af[4];
                    uint32_t ad = smem_addr32(&sA[wn * 32 + mf * 16 + a_row][ks * 16 + a_col8]);
                    ldm_x4(ad, af);
#pragma unroll
                    for (int p = 0; p < 4; p++) {
                        mma16816(d[mf][2 * p],     af, bf[p][0], bf[p][1]);
                        mma16816(d[mf][2 * p + 1], af, bf[p][2], bf[p][3]);
                    }
                }
            }
            __syncthreads();
        }

#pragma unroll
        for (int mf = 0; mf < 2; mf++)
#pragma unroll
            for (int nf = 0; nf < 8; nf++) {
                int colb = mt * 128 + wm * 64 + nf * 8 + (lane & 3) * 2;
#pragma unroll
                for (int e = 0; e < 4; e++) {
                    int s = mf * 2 + (e >> 1);
                    float v = d[mf][nf][e];
                    int m = colb + (e & 1);
                    if (v > t1[s]) { t2[s] = t1[s]; i2[s] = i1[s]; t1[s] = v; i1[s] = m; }
                    else if (v > t2[s]) { t2[s] = v; i2[s] = m; }
                }
            }
    }

#pragma unroll
    for (int off = 1; off <= 2; off <<= 1) {
#pragma unroll
        for (int s = 0; s < 4; s++) {
            float o1 = __shfl_xor_sync(0xFFFFFFFF, t1[s], off);
            float o2 = __shfl_xor_sync(0xFFFFFFFF, t2[s], off);
            int oi1 = __shfl_xor_sync(0xFFFFFFFF, i1[s], off);
            int oi2 = __shfl_xor_sync(0xFFFFFFFF, i2[s], off);
            merge_top2(t1[s], i1[s], t2[s], i2[s], o1, oi1, o2, oi2);
        }
    }

    if ((lane & 3) == 0) {
#pragma unroll
        for (int s = 0; s < 4; s++) {
            int mf = s >> 1;
            int hi = s & 1;
            int row = wn * 32 + mf * 16 + (lane >> 2) + hi * 8;
            sVal[row][wm * 2 + 0] = t1[s];
            sVal[row][wm * 2 + 1] = t2[s];
            sIdx[row][wm * 2 + 0] = i1[s];
            sIdx[row][wm * 2 + 1] = i2[s];
        }
    }
    __syncthreads();

    if (tid < 128) {
        float a1 = sVal[tid][0], a2 = sVal[tid][1];
        int ai1 = sIdx[tid][0], ai2 = sIdx[tid][1];
        merge_top2(a1, ai1, a2, ai2, sVal[tid][2], sIdx[tid][2], sVal[tid][3], sIdx[tid][3]);
        cand[b * FEAT_N + n0 + tid] = make_int2(ai1, ai2);
    }
}

// ---------------------------------------------------------------------------
// Exact fp32 rescore + final reduction
// ---------------------------------------------------------------------------
__global__ void rescore_kernel(const float* __restrict__ xn, const float* __restrict__ sn,
                               const int2* __restrict__ cand, float* __restrict__ rowmax) {
    int gwarp = (blockIdx.x * blockDim.x + threadIdx.x) >> 5;
    int lane = threadIdx.x & 31;
    if (gwarp >= BATCH * FEAT_N) return;
    int b = gwarp >> 12;
    int2 c = cand[gwarp];
    const float4* xr = (const float4*)(xn + (long)gwarp * FEAT_C);
    const float4* s1 = (const float4*)(sn + ((long)(b << 12) + c.x) * FEAT_C);
    const float4* s2 = (const float4*)(sn + ((long)(b << 12) + c.y) * FEAT_C);
    float d1 = 0.f, d2 = 0.f;
#pragma unroll
    for (int i = 0; i < 6; i++) {
        int k = i * 32 + lane;
        float4 xv = xr[k], a = s1[k], bb = s2[k];
        d1 += xv.x * a.x + xv.y * a.y + xv.z * a.z + xv.w * a.w;
        d2 += xv.x * bb.x + xv.y * bb.y + xv.z * bb.z + xv.w * bb.w;
    }
#pragma unroll
    for (int off = 16; off > 0; off >>= 1) {
        d1 += __shfl_xor_sync(0xFFFFFFFF, d1, off);
        d2 += __shfl_xor_sync(0xFFFFFFFF, d2, off);
    }
    if (lane == 0) rowmax[gwarp] = fmaxf(d1, d2);
}

__global__ void loss_kernel(const float* __restrict__ rowmax, float* __restrict__ out) {
    __shared__ float sred[256];
    float s = 0.f;
    for (int i = threadIdx.x; i < BATCH * FEAT_N; i += 256)
        s += 1.0f - rowmax[i];
    sred[threadIdx.x] = s;
    __syncthreads();
    for (int k = 128; k > 0; k >>= 1) {
        if (threadIdx.x < k) sred[threadIdx.x] += sred[threadIdx.x + k];
        __syncthreads();
    }
    if (threadIdx.x == 0) out[0] = sred[0] / (float)(BATCH * FEAT_N);
}

// ---------------------------------------------------------------------------
// Host orchestration
// ---------------------------------------------------------------------------
static void launch_conv_mma(const __half* ih, const __half* il,
                            const __half* wh, const __half* wl, const float* bias,
                            __half* oh, __half* ol,
                            int Cin, int Cout, int H, int W, int inStride, int outStride) {
    dim3 grid(W / 16, H / 8, NBATCH * (Cout / 64));
    conv_mma_kernel<<<grid, 256>>>(ih, il, wh, wl, bias, oh, ol,
                                   Cin, Cout, H, W, inStride, outStride);
}

extern "C" void kernel_launch(void* const* d_in, const int* in_sizes, int n_in,
                              void* d_out, int out_size) {
    const float* outputs = (const float*)d_in[0];
    const float* styles  = (const float*)d_in[1];
    const float* w[7];
    const float* bi[7];
    for (int i = 0; i < 7; i++) {
        w[i]  = (const float*)d_in[2 + 2 * i];
        bi[i] = (const float*)d_in[3 + 2 * i];
    }

    __half *Ah, *Al, *Bh, *Bl, *fh, *fl, *wh, *wl, *xhh;
    float *xn, *rnorm, *rowmax;
    int2* cand;
    cudaGetSymbolAddress((void**)&Ah, g_Ah);
    cudaGetSymbolAddress((void**)&Al, g_Al);
    cudaGetSymbolAddress((void**)&Bh, g_Bh);
    cudaGetSymbolAddress((void**)&Bl, g_Bl);
    cudaGetSymbolAddress((void**)&fh, g_feath);
    cudaGetSymbolAddress((void**)&fl, g_featl);
    cudaGetSymbolAddress((void**)&wh, g_wh);
    cudaGetSymbolAddress((void**)&wl, g_wl);
    cudaGetSymbolAddress((void**)&xn, g_xn);
    cudaGetSymbolAddress((void**)&xhh, g_xh);
    cudaGetSymbolAddress((void**)&rnorm, g_rnorm);
    cudaGetSymbolAddress((void**)&rowmax, g_rowmax);
    cudaGetSymbolAddress((void**)&cand, g_cand);

    // weight fragment prep
    wprep_frag_kernel<<<144, 256>>>(w[1], wh + W12_OFF, wl + W12_OFF, 64, 64);
    wprep_frag_kernel<<<288, 256>>>(w[2], wh + W21_OFF, wl + W21_OFF, 128, 64);
    wprep_frag_kernel<<<576, 256>>>(w[3], wh + W22_OFF, wl + W22_OFF, 128, 128);
    wprep_frag_kernel<<<1152, 256>>>(w[4], wh + W31_OFF, wl + W31_OFF, 256, 128);
    wprep_frag_kernel<<<2304, 256>>>(w[5], wh + W32_OFF, wl + W32_OFF, 256, 256);
    wprep_frag_kernel<<<2304, 256>>>(w[6], wh + W33_OFF, wl + W33_OFF, 256, 256);

    // fused batch-8 feature extraction (outputs: b 0-3, styles: b 4-7)
    conv1_kernel<<<NBATCH * 65536 / 256, 256>>>(outputs, styles, w[0], bi[0], Ah, Al);
    launch_conv_mma(Ah, Al, wh + W12_OFF, wl + W12_OFF, bi[1], Bh, Bl,
                    64, 64, 256, 256, 64, 64);
    maxpool_hl_kernel<<<4096, 256>>>(Bh, Bl, Ah, Al, 64, 256, 256, NBATCH);
    launch_conv_mma(Ah, Al, wh + W21_OFF, wl + W21_OFF, bi[2], Bh, Bl,
                    64, 128, 128, 128, 64, 128);
    launch_conv_mma(Bh, Bl, wh + W22_OFF, wl + W22_OFF, bi[3], Ah, Al,
                    128, 128, 128, 128, 128, 128);
    maxpool_hl_kernel<<<2048, 256>>>(Ah, Al, Bh, Bl, 128, 128, 128, NBATCH);
    launch_conv_mma(Bh, Bl, wh + W31_OFF, wl + W31_OFF, bi[4], fh, fl,
                    128, 256, 64, 64, 128, 768);
    launch_conv_mma(fh, fl, wh + W32_OFF, wl + W32_OFF, bi[5], fh + 256, fl + 256,
                    256, 256, 64, 64, 768, 768);
    launch_conv_mma(fh + 256, fl + 256, wh + W33_OFF, wl + W33_OFF, bi[6],
                    fh + 512, fl + 512, 256, 256, 64, 64, 768, 768);

    norms_nhwc_kernel<<<(NBATCH * FEAT_N * 32 + 255) / 256, 256>>>(fh, fl, rnorm);
    normalize_kernel<<<4096, 256>>>(fh, fl, rnorm, xn, xhh);

    const long soff = (long)BATCH * FEAT_N * FEAT_C;
    dim3 mg(FEAT_N / 128, BATCH);
    maxdot_mma_kernel<<<mg, 256>>>(xhh, xhh + soff, cand);
    rescore_kernel<<<(BATCH * FEAT_N) / 8, 256>>>(xn, xn + soff, cand, rowmax);
    loss_kernel<<<1, 256>>>(rowmax, (float*)d_out);
}